// round 1
// baseline (speedup 1.0000x reference)
#include <cuda_runtime.h>
#include <math.h>
#include <float.h>

#define BATCH 256
#define SEQL  200
#define DIM   256
#define G4    1024
#define NROWS (BATCH*SEQL)   // 51200

// ---------------- device scratch (no allocations allowed) ----------------
__device__ float g_x[NROWS*DIM];
__device__ float g_tfeat[NROWS*64];
__device__ float g_tf[NROWS*DIM];
__device__ float g_xu[NROWS*G4];
__device__ float g_outh[NROWS*DIM];
__device__ float g_whk[NROWS*DIM];
__device__ float g_att1[NROWS*64];
__device__ float g_attn[NROWS*2];
__device__ float g_genx[NROWS*DIM];
__device__ float g_ek[BATCH*DIM];
__device__ float g_ekw1[BATCH*64];
__device__ float g_hbuf[2][BATCH*DIM];
__device__ float g_cbuf[2][BATCH*DIM];
__device__ float g_hmax[BATCH*DIM];

// ---------------- generic SGEMM: C = A(MxK) @ B(KxN) + bias0 + bias1 ----
// BM=128 BN=64 BK=8, 256 threads, per-thread 8x4. Requires M%128==0, N%64==0, K%8==0.
__global__ void sgemm_bias(const float* __restrict__ A, const float* __restrict__ B,
                           float* __restrict__ C,
                           const float* __restrict__ bias0, const float* __restrict__ bias1,
                           int M, int N, int K) {
    __shared__ float As[8][128];
    __shared__ float Bs[8][64];
    int tid = threadIdx.x;
    int bm = blockIdx.y, bn = blockIdx.x;
    const float* Ab = A + (size_t)bm * 128 * K;
    const float* Bb = B + bn * 64;

    int tn = tid & 15;        // 16 col-threads * 4
    int tmRow = tid >> 4;     // 16 row-threads * 8

    int a_m  = tid >> 1;            // 128 rows, 2 threads/row
    int a_k4 = (tid & 1) * 4;       // k offset 0 or 4
    int b_k  = tid >> 5;            // 8 rows
    int b_n  = (tid & 31) * 2;

    float acc[8][4];
#pragma unroll
    for (int i = 0; i < 8; i++)
#pragma unroll
        for (int j = 0; j < 4; j++) acc[i][j] = 0.f;

    for (int k0 = 0; k0 < K; k0 += 8) {
        float4 av = *(const float4*)(Ab + (size_t)a_m * K + k0 + a_k4);
        As[a_k4 + 0][a_m] = av.x;
        As[a_k4 + 1][a_m] = av.y;
        As[a_k4 + 2][a_m] = av.z;
        As[a_k4 + 3][a_m] = av.w;
        float2 bv = *(const float2*)(Bb + (size_t)(k0 + b_k) * N + b_n);
        Bs[b_k][b_n] = bv.x;
        Bs[b_k][b_n + 1] = bv.y;
        __syncthreads();
#pragma unroll
        for (int kk = 0; kk < 8; kk++) {
            float ra[8], rb[4];
#pragma unroll
            for (int i = 0; i < 8; i++) ra[i] = As[kk][tmRow * 8 + i];
#pragma unroll
            for (int j = 0; j < 4; j++) rb[j] = Bs[kk][tn * 4 + j];
#pragma unroll
            for (int i = 0; i < 8; i++)
#pragma unroll
                for (int j = 0; j < 4; j++) acc[i][j] += ra[i] * rb[j];
        }
        __syncthreads();
    }

#pragma unroll
    for (int i = 0; i < 8; i++) {
        int m = bm * 128 + tmRow * 8 + i;
        int n = bn * 64 + tn * 4;
        float4 v;
        v.x = acc[i][0]; v.y = acc[i][1]; v.z = acc[i][2]; v.w = acc[i][3];
        if (bias0) {
            v.x += bias0[n]; v.y += bias0[n + 1]; v.z += bias0[n + 2]; v.w += bias0[n + 3];
        }
        if (bias1) {
            v.x += bias1[n]; v.y += bias1[n + 1]; v.z += bias1[n + 2]; v.w += bias1[n + 3];
        }
        *(float4*)(C + (size_t)m * N + n) = v;
    }
}

// ---------------- small elementwise kernels ----------------
__global__ void k_tfeat(const float* __restrict__ seq_time, const float* __restrict__ sel_w,
                        const float* __restrict__ sel_b) {
    int idx = blockIdx.x * blockDim.x + threadIdx.x;
    if (idx >= NROWS * 64) return;
    int r = idx >> 6, n = idx & 63;
    float t = seq_time[r] * (1.0f / 180.0f);
    float q = t * sel_w[n] + sel_b[n];
    g_tfeat[idx] = 1.0f - tanhf(q * q);
}

__global__ void k_ek() {
    int idx = blockIdx.x * blockDim.x + threadIdx.x;
    if (idx >= BATCH * DIM) return;
    int b = idx >> 8, j = idx & 255;
    g_ek[idx] = g_x[(size_t)b * SEQL * DIM + j];
}

__global__ void k_init() {
    int idx = blockIdx.x * blockDim.x + threadIdx.x;
    if (idx >= BATCH * DIM) return;
    g_hbuf[0][idx] = 0.f; g_hbuf[1][idx] = 0.f;
    g_cbuf[0][idx] = 0.f; g_cbuf[1][idx] = 0.f;
    g_hmax[idx] = -FLT_MAX;
}

// ekw1[b][n] = sum_k ek[b][k] * w1_w[k][n]   (k<256, n<64)
__global__ void k_ekw1(const float* __restrict__ w1_w) {
    int b = blockIdx.x;
    int n = threadIdx.x;  // 64
    float s = 0.f;
    const float* e = g_ek + b * DIM;
#pragma unroll 8
    for (int k = 0; k < DIM; k++) s += e[k] * w1_w[k * 64 + n];
    g_ekw1[b * 64 + n] = s;
}

__global__ void k_attn(const float* __restrict__ w2_w, const float* __restrict__ w2_b) {
    int idx = blockIdx.x * blockDim.x + threadIdx.x;
    if (idx >= BATCH * 199) return;
    int b = idx / 199, s = idx % 199;
    int row = b * SEQL + s;
    const float* a1 = g_att1 + (size_t)row * 64;
    const float* ew = g_ekw1 + b * 64;
    float l0 = w2_b[0], l1 = w2_b[1];
#pragma unroll 8
    for (int n = 0; n < 64; n++) {
        float v = tanhf(a1[n] + ew[n]);
        l0 += v * w2_w[n * 2];
        l1 += v * w2_w[n * 2 + 1];
    }
    float m = fmaxf(l0, l1);
    float e0 = expf(l0 - m), e1 = expf(l1 - m);
    float inv = 1.0f / (e0 + e1);
    g_attn[row * 2]     = e0 * inv;
    g_attn[row * 2 + 1] = e1 * inv;
}

__global__ void k_genx(const float* __restrict__ nn, const float* __restrict__ pn) {
    int idx = blockIdx.x * blockDim.x + threadIdx.x;
    if (idx >= NROWS * DIM) return;
    int j = idx & 255;
    int rs = idx >> 8;          // b*200 + s
    int b = rs / SEQL, s = rs % SEQL;
    float v;
    if (s == 0) {
        v = g_ek[b * DIM + j];
    } else {
        int row = b * SEQL + (s - 1);
        v = g_ek[b * DIM + j] * g_attn[row * 2] + g_whk[(size_t)row * DIM + j] * g_attn[row * 2 + 1];
    }
    g_genx[idx] = v + nn[idx] - pn[idx];
}

__global__ void k_out(const float* __restrict__ out_w, const float* __restrict__ out_b,
                      float* __restrict__ dst) {
    int b = blockIdx.x;
    int j = threadIdx.x;  // 256
    float h = g_hmax[b * DIM + j];
    __shared__ float s0[256], s1[256];
    s0[j] = h * out_w[j * 2];
    s1[j] = h * out_w[j * 2 + 1];
    __syncthreads();
    for (int off = 128; off > 0; off >>= 1) {
        if (j < off) { s0[j] += s0[j + off]; s1[j] += s1[j + off]; }
        __syncthreads();
    }
    if (j == 0) {
        dst[b * 2]     = s0[0] + out_b[0];
        dst[b * 2 + 1] = s1[0] + out_b[1];
    }
}

// ---------------- fused LSTM step ----------------
// grid (8 batch-tiles of 32, 16 unit-tiles of 16), 256 threads, 144KB dyn smem.
#define MB 32
#define UJ 16
template <bool STORE>
__global__ void lstm_step(const float* __restrict__ Hin, const float* __restrict__ Cin,
                          float* __restrict__ Hout, float* __restrict__ Cout,
                          const float* __restrict__ Wall, const float* __restrict__ Wd,
                          const float* __restrict__ Wd_b, int s) {
    extern __shared__ float sm[];
    float* Hs = sm;                     // [MB][DIM]
    float* Cs = Hs + MB * DIM;          // [MB][DIM]
    float* Ws = Cs + MB * DIM;          // [DIM][5][UJ] : k*80 + g*16 + jl

    int tid = threadIdx.x;
    int b0 = blockIdx.x * MB;
    int j0 = blockIdx.y * UJ;

    const float4* hin4 = (const float4*)(Hin + b0 * DIM);
    const float4* cin4 = (const float4*)(Cin + b0 * DIM);
    for (int i = tid; i < MB * DIM / 4; i += 256) {
        ((float4*)Hs)[i] = hin4[i];
        ((float4*)Cs)[i] = cin4[i];
    }
    for (int i = tid; i < DIM * 5 * UJ; i += 256) {
        int k = i / (5 * UJ);
        int r = i % (5 * UJ);
        int g = r / UJ;
        int jl = r % UJ;
        Ws[i] = (g < 4) ? Wall[k * G4 + g * DIM + j0 + jl] : Wd[k * DIM + j0 + jl];
    }
    __syncthreads();

    int jl = tid % UJ;
    int ml = (tid / UJ) * 2;

    float accf[2] = {0.f, 0.f}, acci[2] = {0.f, 0.f}, acco[2] = {0.f, 0.f};
    float accc[2] = {0.f, 0.f}, accd[2] = {0.f, 0.f};
    const float* h0p = Hs + ml * DIM;
    const float* h1p = h0p + DIM;
    const float* c0p = Cs + ml * DIM;
    const float* c1p = c0p + DIM;
    const float* wp = Ws + jl;

#pragma unroll 4
    for (int k = 0; k < DIM; k++) {
        float wf = wp[0], wi = wp[16], wo = wp[32], wc = wp[48], wd = wp[64];
        wp += 80;
        float h0 = h0p[k], h1 = h1p[k];
        float cc0 = c0p[k], cc1 = c1p[k];
        accf[0] += h0 * wf; accf[1] += h1 * wf;
        acci[0] += h0 * wi; acci[1] += h1 * wi;
        acco[0] += h0 * wo; acco[1] += h1 * wo;
        accc[0] += h0 * wc; accc[1] += h1 * wc;
        accd[0] += cc0 * wd; accd[1] += cc1 * wd;
    }

    int j = j0 + jl;
    float wdb = Wd_b[j];
#pragma unroll
    for (int r = 0; r < 2; r++) {
        int b = b0 + ml + r;
        size_t rowi = (size_t)b * SEQL + s;
        const float* xrow = g_xu + rowi * G4;
        float gf = 1.f / (1.f + expf(-(accf[r] + xrow[j])));
        float gi = 1.f / (1.f + expf(-(acci[r] + xrow[DIM + j])));
        float go = 1.f / (1.f + expf(-(acco[r] + xrow[2 * DIM + j])));
        float gc = 1.f / (1.f + expf(-(accc[r] + xrow[3 * DIM + j])));
        float cs1 = tanhf(accd[r] + wdb);
        float cold = Cs[(ml + r) * DIM + j];
        float ts = g_tf[rowi * DIM + j];
        float cadj = cold - cs1 + cs1 * ts;
        float cnew = gf * cadj + gi * gc;
        float hnew = go * tanhf(cnew);
        int oi = b * DIM + j;
        Hout[oi] = hnew;
        Cout[oi] = cnew;
        if (STORE) g_outh[rowi * DIM + j] = hnew;
        float hm = g_hmax[oi];
        g_hmax[oi] = hnew > hm ? hnew : hm;
    }
}

// ---------------- host launcher ----------------
extern "C" void kernel_launch(void* const* d_in, const int* in_sizes, int n_in,
                              void* d_out, int out_size) {
    (void)in_sizes; (void)n_in; (void)out_size;
    const float* input_seqs = (const float*)d_in[0];
    const float* seq_time   = (const float*)d_in[3];
    const float* nn         = (const float*)d_in[6];
    const float* pn         = (const float*)d_in[7];
    const float* emb2_w = (const float*)d_in[9];
    const float* emb2_b = (const float*)d_in[10];
    const float* Wall_w = (const float*)d_in[11];
    const float* Wall_b = (const float*)d_in[12];
    const float* Uall_w = (const float*)d_in[13];
    const float* Uall_b = (const float*)d_in[14];
    const float* Wd_w   = (const float*)d_in[15];
    const float* Wd_b   = (const float*)d_in[16];
    const float* time_w = (const float*)d_in[17];
    const float* time_b = (const float*)d_in[18];
    const float* sel_w  = (const float*)d_in[19];
    const float* sel_b  = (const float*)d_in[20];
    const float* whk_w  = (const float*)d_in[21];
    const float* whk_b  = (const float*)d_in[22];
    const float* w1_w   = (const float*)d_in[23];
    const float* w1_b   = (const float*)d_in[24];
    const float* w2_w   = (const float*)d_in[25];
    const float* w2_b   = (const float*)d_in[26];
    const float* out_w  = (const float*)d_in[27];
    const float* out_b  = (const float*)d_in[28];
    float* out = (float*)d_out;

    float *px, *ptfeat, *ptf, *pxu, *pouth, *pwhk, *patt1, *pgenx, *pH, *pC;
    cudaGetSymbolAddress((void**)&px, g_x);
    cudaGetSymbolAddress((void**)&ptfeat, g_tfeat);
    cudaGetSymbolAddress((void**)&ptf, g_tf);
    cudaGetSymbolAddress((void**)&pxu, g_xu);
    cudaGetSymbolAddress((void**)&pouth, g_outh);
    cudaGetSymbolAddress((void**)&pwhk, g_whk);
    cudaGetSymbolAddress((void**)&patt1, g_att1);
    cudaGetSymbolAddress((void**)&pgenx, g_genx);
    cudaGetSymbolAddress((void**)&pH, g_hbuf);
    cudaGetSymbolAddress((void**)&pC, g_cbuf);

    const int SMEM_STEP = (2 * MB * DIM + 5 * UJ * DIM) * 4;  // 147456 B
    cudaFuncSetAttribute((const void*)lstm_step<true>,
                         cudaFuncAttributeMaxDynamicSharedMemorySize, SMEM_STEP);
    cudaFuncSetAttribute((const void*)lstm_step<false>,
                         cudaFuncAttributeMaxDynamicSharedMemorySize, SMEM_STEP);

    dim3 t256(256);

    // time feature: tfeat then GEMM @ time_w (+time_b)
    k_tfeat<<<(NROWS * 64 + 255) / 256, t256>>>(seq_time, sel_w, sel_b);
    sgemm_bias<<<dim3(DIM / 64, NROWS / 128), t256>>>(ptfeat, time_w, ptf, time_b, nullptr,
                                                      NROWS, DIM, 64);
    // x = input @ emb2 + b
    sgemm_bias<<<dim3(DIM / 64, NROWS / 128), t256>>>(input_seqs, emb2_w, px, emb2_b, nullptr,
                                                      NROWS, DIM, DIM);
    k_ek<<<(BATCH * DIM + 255) / 256, t256>>>();
    // xu1 = x @ Uall + (Uall_b + Wall_b)
    sgemm_bias<<<dim3(G4 / 64, NROWS / 128), t256>>>(px, Uall_w, pxu, Uall_b, Wall_b,
                                                     NROWS, G4, DIM);
    // LSTM 1
    k_init<<<(BATCH * DIM + 255) / 256, t256>>>();
    {
        int p = 0;
        for (int s = 0; s < SEQL; s++) {
            lstm_step<true><<<dim3(BATCH / MB, DIM / UJ), t256, SMEM_STEP>>>(
                pH + p * BATCH * DIM, pC + p * BATCH * DIM,
                pH + (1 - p) * BATCH * DIM, pC + (1 - p) * BATCH * DIM,
                Wall_w, Wd_w, Wd_b, s);
            p ^= 1;
        }
    }
    k_out<<<BATCH, t256>>>(out_w, out_b, out);  // out -> [0, 512)

    // whk, attention, gen_x
    sgemm_bias<<<dim3(DIM / 64, NROWS / 128), t256>>>(pouth, whk_w, pwhk, whk_b, nullptr,
                                                      NROWS, DIM, DIM);
    k_ekw1<<<BATCH, 64>>>(w1_w);
    sgemm_bias<<<dim3(1, NROWS / 128), t256>>>(pwhk, w1_w + 256 * 64, patt1, w1_b, nullptr,
                                               NROWS, 64, DIM);
    k_attn<<<(BATCH * 199 + 255) / 256, t256>>>(w2_w, w2_b);
    k_genx<<<(NROWS * DIM + 255) / 256, t256>>>(nn, pn);

    // xu2 = gen_x @ Uall + (Uall_b + Wall_b)
    sgemm_bias<<<dim3(G4 / 64, NROWS / 128), t256>>>(pgenx, Uall_w, pxu, Uall_b, Wall_b,
                                                     NROWS, G4, DIM);
    // LSTM 2 (no output storage, only running max)
    k_init<<<(BATCH * DIM + 255) / 256, t256>>>();
    {
        int p = 0;
        for (int s = 0; s < SEQL; s++) {
            lstm_step<false><<<dim3(BATCH / MB, DIM / UJ), t256, SMEM_STEP>>>(
                pH + p * BATCH * DIM, pC + p * BATCH * DIM,
                pH + (1 - p) * BATCH * DIM, pC + (1 - p) * BATCH * DIM,
                Wall_w, Wd_w, Wd_b, s);
            p ^= 1;
        }
    }
    k_out<<<BATCH, t256>>>(out_w, out_b, out + 512);  // gen_out -> [512, 1024)

    // pass-throughs: predicted_noise then normal_noise
    cudaMemcpyAsync(out + 1024, pn, (size_t)NROWS * DIM * sizeof(float),
                    cudaMemcpyDeviceToDevice);
    cudaMemcpyAsync(out + 1024 + (size_t)NROWS * DIM, nn, (size_t)NROWS * DIM * sizeof(float),
                    cudaMemcpyDeviceToDevice);
}

// round 2
// speedup vs baseline: 1.6084x; 1.6084x over previous
#include <cuda_runtime.h>
#include <math.h>
#include <float.h>

#define BATCH 256
#define SEQL  200
#define DIM   256
#define G4    1024
#define NROWS (BATCH*SEQL)   // 51200
#define WSTR  260            // padded k-stride for packed weights (2-phase LDS.128)

typedef unsigned long long u64;

// ---------------- device scratch (no allocations allowed) ----------------
__device__ float g_x[NROWS*DIM];
__device__ float g_tfeat[NROWS*64];
__device__ float g_tf[NROWS*DIM];
__device__ float g_xu[NROWS*G4];
__device__ float g_outh[NROWS*DIM];
__device__ float g_whk[NROWS*DIM];
__device__ float g_att1[NROWS*64];
__device__ float g_attn[NROWS*2];
__device__ float g_genx[NROWS*DIM];
__device__ float g_ek[BATCH*DIM];
__device__ float g_ekw1[BATCH*64];
__device__ float g_hbuf[2][BATCH*DIM];
__device__ float g_cbuf[2][BATCH*DIM];
__device__ float g_hmax[BATCH*DIM];
__device__ float g_wpack[16*5*16*WSTR];   // [jblk][g][jl][k(+pad)]

// ---------------- tf32 helpers ----------------
__device__ __forceinline__ unsigned f2tf(float f) {
    unsigned u; asm("cvt.rna.tf32.f32 %0, %1;" : "=r"(u) : "f"(f)); return u;
}
__device__ __forceinline__ void fma2(u64 &d, u64 a, u64 b) {
    asm("fma.rn.f32x2 %0, %1, %2, %3;" : "=l"(d) : "l"(a), "l"(b), "l"(d));
}
__device__ __forceinline__ float lo32(u64 v) { return __uint_as_float((unsigned)v); }
__device__ __forceinline__ float hi32(u64 v) { return __uint_as_float((unsigned)(v >> 32)); }

// ---------------- tf32 tensor-core GEMM ----------------
// C(M,N) = A(M,K) @ B(K,N) + bias0 + bias1.  BM=128 BN=64 BK=32, 256 threads.
// Requires M%128==0, N%64==0, K%32==0.
__global__ void gemm_tf32(const float* __restrict__ A, const float* __restrict__ B,
                          float* __restrict__ C,
                          const float* __restrict__ bias0, const float* __restrict__ bias1,
                          int M, int N, int K) {
    __shared__ unsigned As[128][36];   // [m][k], pad 4 -> conflict-free frag loads
    __shared__ unsigned Bs[32][72];    // [k][n], pad 8 -> conflict-free frag loads

    int tid  = threadIdx.x;
    int lane = tid & 31, wid = tid >> 5;
    int wm = wid & 3, wn = wid >> 2;          // warps 4(M) x 2(N)
    int gid = lane >> 2, tid4 = lane & 3;
    int bm = blockIdx.y, bn = blockIdx.x;

    const float* Ab = A + (size_t)bm * 128 * K;
    const float* Bb = B + (size_t)bn * 64;

    int am[4], akq[4];
#pragma unroll
    for (int it = 0; it < 4; it++) { int f = it * 256 + tid; am[it] = f >> 3; akq[it] = f & 7; }
    int bn4[2], bkk[2];
#pragma unroll
    for (int it = 0; it < 2; it++) { int f = it * 256 + tid; bn4[it] = f & 15; bkk[it] = f >> 4; }

    float acc[2][4][4];
#pragma unroll
    for (int i = 0; i < 2; i++)
#pragma unroll
        for (int j = 0; j < 4; j++)
#pragma unroll
            for (int q = 0; q < 4; q++) acc[i][j][q] = 0.f;

    float4 ar[4], br[2];
#pragma unroll
    for (int it = 0; it < 4; it++)
        ar[it] = *(const float4*)(Ab + (size_t)am[it] * K + akq[it] * 4);
#pragma unroll
    for (int it = 0; it < 2; it++)
        br[it] = *(const float4*)(Bb + (size_t)bkk[it] * N + bn4[it] * 4);

    int nch = K >> 5;
    for (int ch = 0; ch < nch; ch++) {
        // commit staged regs to smem (tf32 convert at store)
#pragma unroll
        for (int it = 0; it < 4; it++) {
            unsigned* p = &As[am[it]][akq[it] * 4];
            p[0] = f2tf(ar[it].x); p[1] = f2tf(ar[it].y);
            p[2] = f2tf(ar[it].z); p[3] = f2tf(ar[it].w);
        }
#pragma unroll
        for (int it = 0; it < 2; it++) {
            unsigned* p = &Bs[bkk[it]][bn4[it] * 4];
            p[0] = f2tf(br[it].x); p[1] = f2tf(br[it].y);
            p[2] = f2tf(br[it].z); p[3] = f2tf(br[it].w);
        }
        __syncthreads();
        // prefetch next chunk while computing this one
        if (ch + 1 < nch) {
            int k0 = (ch + 1) << 5;
#pragma unroll
            for (int it = 0; it < 4; it++)
                ar[it] = *(const float4*)(Ab + (size_t)am[it] * K + k0 + akq[it] * 4);
#pragma unroll
            for (int it = 0; it < 2; it++)
                br[it] = *(const float4*)(Bb + (size_t)(k0 + bkk[it]) * N + bn4[it] * 4);
        }
#pragma unroll
        for (int kc = 0; kc < 32; kc += 8) {
            unsigned af[2][4], bf[4][2];
#pragma unroll
            for (int s = 0; s < 2; s++) {
                int rm = wm * 32 + s * 16 + gid;
                af[s][0] = As[rm][kc + tid4];
                af[s][1] = As[rm + 8][kc + tid4];
                af[s][2] = As[rm][kc + tid4 + 4];
                af[s][3] = As[rm + 8][kc + tid4 + 4];
            }
#pragma unroll
            for (int s = 0; s < 4; s++) {
                int cb = wn * 32 + s * 8 + gid;
                bf[s][0] = Bs[kc + tid4][cb];
                bf[s][1] = Bs[kc + tid4 + 4][cb];
            }
#pragma unroll
            for (int i = 0; i < 2; i++)
#pragma unroll
                for (int j = 0; j < 4; j++)
                    asm volatile(
                        "mma.sync.aligned.m16n8k8.row.col.f32.tf32.tf32.f32 "
                        "{%0,%1,%2,%3}, {%4,%5,%6,%7}, {%8,%9}, {%0,%1,%2,%3};"
                        : "+f"(acc[i][j][0]), "+f"(acc[i][j][1]),
                          "+f"(acc[i][j][2]), "+f"(acc[i][j][3])
                        : "r"(af[i][0]), "r"(af[i][1]), "r"(af[i][2]), "r"(af[i][3]),
                          "r"(bf[j][0]), "r"(bf[j][1]));
        }
        __syncthreads();
    }

#pragma unroll
    for (int i = 0; i < 2; i++) {
        int r0 = bm * 128 + wm * 32 + i * 16 + gid;
#pragma unroll
        for (int j = 0; j < 4; j++) {
            int col = bn * 64 + wn * 32 + j * 8 + tid4 * 2;
            float bb0 = 0.f, bb1 = 0.f;
            if (bias0) { bb0 += bias0[col]; bb1 += bias0[col + 1]; }
            if (bias1) { bb0 += bias1[col]; bb1 += bias1[col + 1]; }
            float2 v0; v0.x = acc[i][j][0] + bb0; v0.y = acc[i][j][1] + bb1;
            float2 v1; v1.x = acc[i][j][2] + bb0; v1.y = acc[i][j][3] + bb1;
            *(float2*)(C + (size_t)r0 * N + col) = v0;
            *(float2*)(C + (size_t)(r0 + 8) * N + col) = v1;
        }
    }
}

// ---------------- weight pre-pack for the LSTM step ----------------
// g_wpack[jblk][g][jl][k] with k-stride WSTR. g=0..3: Wall cols, g=4: Wd cols.
__global__ void k_pack(const float* __restrict__ Wall, const float* __restrict__ Wd) {
    int idx = blockIdx.x * 256 + threadIdx.x;
    if (idx >= 16 * 5 * 256 * 16) return;
    int jl = idx & 15;
    int rest = idx >> 4;
    int k = rest & 255;
    int rest2 = rest >> 8;            // jblk*5 + g
    int g = rest2 % 5;
    int jblk = rest2 / 5;
    int j = jblk * 16 + jl;
    float v = (g < 4) ? Wall[(size_t)k * G4 + g * DIM + j]
                      : Wd[(size_t)k * DIM + j];
    g_wpack[(size_t)jblk * (5 * 16 * WSTR) + (g * 16 + jl) * WSTR + k] = v;
}

// ---------------- small elementwise kernels ----------------
__global__ void k_tfeat(const float* __restrict__ seq_time, const float* __restrict__ sel_w,
                        const float* __restrict__ sel_b) {
    int idx = blockIdx.x * blockDim.x + threadIdx.x;
    if (idx >= NROWS * 64) return;
    int r = idx >> 6, n = idx & 63;
    float t = seq_time[r] * (1.0f / 180.0f);
    float q = t * sel_w[n] + sel_b[n];
    g_tfeat[idx] = 1.0f - tanhf(q * q);
}

__global__ void k_ek() {
    int idx = blockIdx.x * blockDim.x + threadIdx.x;
    if (idx >= BATCH * DIM) return;
    int b = idx >> 8, j = idx & 255;
    g_ek[idx] = g_x[(size_t)b * SEQL * DIM + j];
}

__global__ void k_init() {
    int idx = blockIdx.x * blockDim.x + threadIdx.x;
    if (idx >= BATCH * DIM) return;
    g_hbuf[0][idx] = 0.f; g_hbuf[1][idx] = 0.f;
    g_cbuf[0][idx] = 0.f; g_cbuf[1][idx] = 0.f;
    g_hmax[idx] = -FLT_MAX;
}

__global__ void k_ekw1(const float* __restrict__ w1_w) {
    int b = blockIdx.x;
    int n = threadIdx.x;  // 64
    float s = 0.f;
    const float* e = g_ek + b * DIM;
#pragma unroll 8
    for (int k = 0; k < DIM; k++) s += e[k] * w1_w[k * 64 + n];
    g_ekw1[b * 64 + n] = s;
}

__global__ void k_attn(const float* __restrict__ w2_w, const float* __restrict__ w2_b) {
    int idx = blockIdx.x * blockDim.x + threadIdx.x;
    if (idx >= BATCH * 199) return;
    int b = idx / 199, s = idx % 199;
    int row = b * SEQL + s;
    const float* a1 = g_att1 + (size_t)row * 64;
    const float* ew = g_ekw1 + b * 64;
    float l0 = w2_b[0], l1 = w2_b[1];
#pragma unroll 8
    for (int n = 0; n < 64; n++) {
        float v = tanhf(a1[n] + ew[n]);
        l0 += v * w2_w[n * 2];
        l1 += v * w2_w[n * 2 + 1];
    }
    float m = fmaxf(l0, l1);
    float e0 = expf(l0 - m), e1 = expf(l1 - m);
    float inv = 1.0f / (e0 + e1);
    g_attn[row * 2]     = e0 * inv;
    g_attn[row * 2 + 1] = e1 * inv;
}

__global__ void k_genx(const float* __restrict__ nn, const float* __restrict__ pn) {
    int idx = blockIdx.x * blockDim.x + threadIdx.x;
    if (idx >= NROWS * DIM) return;
    int j = idx & 255;
    int rs = idx >> 8;
    int b = rs / SEQL, s = rs % SEQL;
    float v;
    if (s == 0) {
        v = g_ek[b * DIM + j];
    } else {
        int row = b * SEQL + (s - 1);
        v = g_ek[b * DIM + j] * g_attn[row * 2] + g_whk[(size_t)row * DIM + j] * g_attn[row * 2 + 1];
    }
    g_genx[idx] = v + nn[idx] - pn[idx];
}

__global__ void k_out(const float* __restrict__ out_w, const float* __restrict__ out_b,
                      float* __restrict__ dst) {
    int b = blockIdx.x;
    int j = threadIdx.x;  // 256
    float h = g_hmax[b * DIM + j];
    __shared__ float s0[256], s1[256];
    s0[j] = h * out_w[j * 2];
    s1[j] = h * out_w[j * 2 + 1];
    __syncthreads();
    for (int off = 128; off > 0; off >>= 1) {
        if (j < off) { s0[j] += s0[j + off]; s1[j] += s1[j + off]; }
        __syncthreads();
    }
    if (j == 0) {
        dst[b * 2]     = s0[0] + out_b[0];
        dst[b * 2 + 1] = s1[0] + out_b[1];
    }
}

// ---------------- fused LSTM step (f32x2 + float4 smem) ----------------
// grid (8 batch-tiles of 32, 16 unit-tiles of 16), 256 threads.
#define MB 32
#define UJ 16
template <bool STORE>
__global__ void lstm_step(const float* __restrict__ Hin, const float* __restrict__ Cin,
                          float* __restrict__ Hout, float* __restrict__ Cout,
                          const float* __restrict__ Wd_b, int s) {
    extern __shared__ float sm[];
    float* Hs = sm;                     // [MB][DIM]
    float* Cs = Hs + MB * DIM;          // [MB][DIM]
    float* Ws = Cs + MB * DIM;          // [5][UJ][WSTR]

    int tid = threadIdx.x;
    int b0 = blockIdx.x * MB;
    int jblk = blockIdx.y;
    int j0 = jblk * UJ;

    const float4* hin4 = (const float4*)(Hin + b0 * DIM);
    const float4* cin4 = (const float4*)(Cin + b0 * DIM);
#pragma unroll
    for (int i = tid; i < MB * DIM / 4; i += 256) {
        ((float4*)Hs)[i] = hin4[i];
        ((float4*)Cs)[i] = cin4[i];
    }
    const float4* wsrc = (const float4*)(g_wpack + (size_t)jblk * (5 * 16 * WSTR));
    for (int i = tid; i < 5 * 16 * WSTR / 4; i += 256)
        ((float4*)Ws)[i] = wsrc[i];
    __syncthreads();

    int jl = tid & 15;
    int ml = (tid >> 4) * 2;

    const ulonglong2* wq0 = (const ulonglong2*)(Ws + (0 * 16 + jl) * WSTR);
    const ulonglong2* wq1 = (const ulonglong2*)(Ws + (1 * 16 + jl) * WSTR);
    const ulonglong2* wq2 = (const ulonglong2*)(Ws + (2 * 16 + jl) * WSTR);
    const ulonglong2* wq3 = (const ulonglong2*)(Ws + (3 * 16 + jl) * WSTR);
    const ulonglong2* wq4 = (const ulonglong2*)(Ws + (4 * 16 + jl) * WSTR);
    const ulonglong2* h0q = (const ulonglong2*)(Hs + ml * DIM);
    const ulonglong2* h1q = (const ulonglong2*)(Hs + (ml + 1) * DIM);
    const ulonglong2* c0q = (const ulonglong2*)(Cs + ml * DIM);
    const ulonglong2* c1q = (const ulonglong2*)(Cs + (ml + 1) * DIM);

    u64 ax[5][2], ay[5][2];
#pragma unroll
    for (int g = 0; g < 5; g++) { ax[g][0] = 0; ax[g][1] = 0; ay[g][0] = 0; ay[g][1] = 0; }

#pragma unroll 4
    for (int k4 = 0; k4 < DIM / 4; k4++) {
        ulonglong2 w0 = wq0[k4], w1 = wq1[k4], w2 = wq2[k4], w3 = wq3[k4], w4 = wq4[k4];
        ulonglong2 hv0 = h0q[k4], hv1 = h1q[k4];
        ulonglong2 cv0 = c0q[k4], cv1 = c1q[k4];
        fma2(ax[0][0], hv0.x, w0.x); fma2(ay[0][0], hv0.y, w0.y);
        fma2(ax[0][1], hv1.x, w0.x); fma2(ay[0][1], hv1.y, w0.y);
        fma2(ax[1][0], hv0.x, w1.x); fma2(ay[1][0], hv0.y, w1.y);
        fma2(ax[1][1], hv1.x, w1.x); fma2(ay[1][1], hv1.y, w1.y);
        fma2(ax[2][0], hv0.x, w2.x); fma2(ay[2][0], hv0.y, w2.y);
        fma2(ax[2][1], hv1.x, w2.x); fma2(ay[2][1], hv1.y, w2.y);
        fma2(ax[3][0], hv0.x, w3.x); fma2(ay[3][0], hv0.y, w3.y);
        fma2(ax[3][1], hv1.x, w3.x); fma2(ay[3][1], hv1.y, w3.y);
        fma2(ax[4][0], cv0.x, w4.x); fma2(ay[4][0], cv0.y, w4.y);
        fma2(ax[4][1], cv1.x, w4.x); fma2(ay[4][1], cv1.y, w4.y);
    }

    float av[5][2];
#pragma unroll
    for (int g = 0; g < 5; g++)
#pragma unroll
        for (int r = 0; r < 2; r++)
            av[g][r] = (lo32(ax[g][r]) + hi32(ax[g][r])) + (lo32(ay[g][r]) + hi32(ay[g][r]));

    int j = j0 + jl;
    float wdb = Wd_b[j];
#pragma unroll
    for (int r = 0; r < 2; r++) {
        int b = b0 + ml + r;
        size_t rowi = (size_t)b * SEQL + s;
        const float* xrow = g_xu + rowi * G4;
        float gf = 1.f / (1.f + expf(-(av[0][r] + xrow[j])));
        float gi = 1.f / (1.f + expf(-(av[1][r] + xrow[DIM + j])));
        float go = 1.f / (1.f + expf(-(av[2][r] + xrow[2 * DIM + j])));
        float gc = 1.f / (1.f + expf(-(av[3][r] + xrow[3 * DIM + j])));
        float cs1 = tanhf(av[4][r] + wdb);
        float cold = Cs[(ml + r) * DIM + j];
        float ts = g_tf[rowi * DIM + j];
        float cadj = cold - cs1 + cs1 * ts;
        float cnew = gf * cadj + gi * gc;
        float hnew = go * tanhf(cnew);
        int oi = b * DIM + j;
        Hout[oi] = hnew;
        Cout[oi] = cnew;
        if (STORE) g_outh[rowi * DIM + j] = hnew;
        float hm = g_hmax[oi];
        g_hmax[oi] = hnew > hm ? hnew : hm;
    }
}

// ---------------- host launcher ----------------
extern "C" void kernel_launch(void* const* d_in, const int* in_sizes, int n_in,
                              void* d_out, int out_size) {
    (void)in_sizes; (void)n_in; (void)out_size;
    const float* input_seqs = (const float*)d_in[0];
    const float* seq_time   = (const float*)d_in[3];
    const float* nn         = (const float*)d_in[6];
    const float* pn         = (const float*)d_in[7];
    const float* emb2_w = (const float*)d_in[9];
    const float* emb2_b = (const float*)d_in[10];
    const float* Wall_w = (const float*)d_in[11];
    const float* Wall_b = (const float*)d_in[12];
    const float* Uall_w = (const float*)d_in[13];
    const float* Uall_b = (const float*)d_in[14];
    const float* Wd_w   = (const float*)d_in[15];
    const float* Wd_b   = (const float*)d_in[16];
    const float* time_w = (const float*)d_in[17];
    const float* time_b = (const float*)d_in[18];
    const float* sel_w  = (const float*)d_in[19];
    const float* sel_b  = (const float*)d_in[20];
    const float* whk_w  = (const float*)d_in[21];
    const float* whk_b  = (const float*)d_in[22];
    const float* w1_w   = (const float*)d_in[23];
    const float* w1_b   = (const float*)d_in[24];
    const float* w2_w   = (const float*)d_in[25];
    const float* w2_b   = (const float*)d_in[26];
    const float* out_w  = (const float*)d_in[27];
    const float* out_b  = (const float*)d_in[28];
    float* out = (float*)d_out;

    float *px, *ptfeat, *ptf, *pxu, *pouth, *pwhk, *patt1, *pgenx, *pH, *pC;
    cudaGetSymbolAddress((void**)&px, g_x);
    cudaGetSymbolAddress((void**)&ptfeat, g_tfeat);
    cudaGetSymbolAddress((void**)&ptf, g_tf);
    cudaGetSymbolAddress((void**)&pxu, g_xu);
    cudaGetSymbolAddress((void**)&pouth, g_outh);
    cudaGetSymbolAddress((void**)&pwhk, g_whk);
    cudaGetSymbolAddress((void**)&patt1, g_att1);
    cudaGetSymbolAddress((void**)&pgenx, g_genx);
    cudaGetSymbolAddress((void**)&pH, g_hbuf);
    cudaGetSymbolAddress((void**)&pC, g_cbuf);

    const int SMEM_STEP = (2 * MB * DIM + 5 * UJ * WSTR) * 4;  // 148736 B
    cudaFuncSetAttribute((const void*)lstm_step<true>,
                         cudaFuncAttributeMaxDynamicSharedMemorySize, SMEM_STEP);
    cudaFuncSetAttribute((const void*)lstm_step<false>,
                         cudaFuncAttributeMaxDynamicSharedMemorySize, SMEM_STEP);

    dim3 t256(256);

    // pack recurrence weights once (cheap; graph replays it, still correct)
    k_pack<<<(16 * 5 * 256 * 16) / 256, t256>>>(Wall_w, Wd_w);

    // time feature: tfeat then GEMM @ time_w (+time_b)
    k_tfeat<<<(NROWS * 64 + 255) / 256, t256>>>(seq_time, sel_w, sel_b);
    gemm_tf32<<<dim3(DIM / 64, NROWS / 128), t256>>>(ptfeat, time_w, ptf, time_b, nullptr,
                                                     NROWS, DIM, 64);
    // x = input @ emb2 + b
    gemm_tf32<<<dim3(DIM / 64, NROWS / 128), t256>>>(input_seqs, emb2_w, px, emb2_b, nullptr,
                                                     NROWS, DIM, DIM);
    k_ek<<<(BATCH * DIM + 255) / 256, t256>>>();
    // xu1 = x @ Uall + (Uall_b + Wall_b)
    gemm_tf32<<<dim3(G4 / 64, NROWS / 128), t256>>>(px, Uall_w, pxu, Uall_b, Wall_b,
                                                    NROWS, G4, DIM);
    // LSTM 1
    k_init<<<(BATCH * DIM + 255) / 256, t256>>>();
    {
        int p = 0;
        for (int s = 0; s < SEQL; s++) {
            lstm_step<true><<<dim3(BATCH / MB, DIM / UJ), t256, SMEM_STEP>>>(
                pH + p * BATCH * DIM, pC + p * BATCH * DIM,
                pH + (1 - p) * BATCH * DIM, pC + (1 - p) * BATCH * DIM,
                Wd_b, s);
            p ^= 1;
        }
    }
    k_out<<<BATCH, t256>>>(out_w, out_b, out);  // out -> [0, 512)

    // whk, attention, gen_x
    gemm_tf32<<<dim3(DIM / 64, NROWS / 128), t256>>>(pouth, whk_w, pwhk, whk_b, nullptr,
                                                     NROWS, DIM, DIM);
    k_ekw1<<<BATCH, 64>>>(w1_w);
    gemm_tf32<<<dim3(1, NROWS / 128), t256>>>(pwhk, w1_w + 256 * 64, patt1, w1_b, nullptr,
                                              NROWS, 64, DIM);
    k_attn<<<(BATCH * 199 + 255) / 256, t256>>>(w2_w, w2_b);
    k_genx<<<(NROWS * DIM + 255) / 256, t256>>>(nn, pn);

    // xu2 = gen_x @ Uall + (Uall_b + Wall_b)
    gemm_tf32<<<dim3(G4 / 64, NROWS / 128), t256>>>(pgenx, Uall_w, pxu, Uall_b, Wall_b,
                                                    NROWS, G4, DIM);
    // LSTM 2 (no stored outputs, only running max)
    k_init<<<(BATCH * DIM + 255) / 256, t256>>>();
    {
        int p = 0;
        for (int s = 0; s < SEQL; s++) {
            lstm_step<false><<<dim3(BATCH / MB, DIM / UJ), t256, SMEM_STEP>>>(
                pH + p * BATCH * DIM, pC + p * BATCH * DIM,
                pH + (1 - p) * BATCH * DIM, pC + (1 - p) * BATCH * DIM,
                Wd_b, s);
            p ^= 1;
        }
    }
    k_out<<<BATCH, t256>>>(out_w, out_b, out + 512);  // gen_out -> [512, 1024)

    // pass-throughs: predicted_noise then normal_noise
    cudaMemcpyAsync(out + 1024, pn, (size_t)NROWS * DIM * sizeof(float),
                    cudaMemcpyDeviceToDevice);
    cudaMemcpyAsync(out + 1024 + (size_t)NROWS * DIM, nn, (size_t)NROWS * DIM * sizeof(float),
                    cudaMemcpyDeviceToDevice);
}

// round 3
// speedup vs baseline: 1.7692x; 1.1000x over previous
#include <cuda_runtime.h>
#include <math.h>
#include <float.h>

#define BATCH 256
#define SEQL  200
#define DIM   256
#define G4    1024
#define NROWS (BATCH*SEQL)   // 51200
#define WSTR  260            // padded k-stride for packed weights (2-phase LDS.128)
#define MB 32
#define UJ 16
#define NBLK 128             // 8 batch-tiles x 16 j-tiles

typedef unsigned long long u64;

// ---------------- device scratch (no allocations allowed) ----------------
__device__ float g_x[NROWS*DIM];
__device__ float g_tfeat[NROWS*64];
__device__ float g_tf[NROWS*DIM];
__device__ float g_xu[NROWS*G4];
__device__ float g_outh[NROWS*DIM];
__device__ float g_whk[NROWS*DIM];
__device__ float g_att1[NROWS*64];
__device__ float g_attn[NROWS*2];
__device__ float g_genx[NROWS*DIM];
__device__ float g_ek[BATCH*DIM];
__device__ float g_ekw1[BATCH*64];
__device__ float g_hbuf[2][BATCH*DIM];
__device__ float g_cbuf[2][BATCH*DIM];
__device__ float g_hmax[BATCH*DIM];
__device__ float g_wpack[16*5*16*WSTR];   // [jblk][g][jl][k(+pad)]
__device__ unsigned g_bar;                // grid barrier counter (memset to 0 pre-launch)

// ---------------- tf32 helpers ----------------
__device__ __forceinline__ unsigned f2tf(float f) {
    unsigned u; asm("cvt.rna.tf32.f32 %0, %1;" : "=r"(u) : "f"(f)); return u;
}
__device__ __forceinline__ void fma2(u64 &d, u64 a, u64 b) {
    asm("fma.rn.f32x2 %0, %1, %2, %3;" : "=l"(d) : "l"(a), "l"(b), "l"(d));
}
__device__ __forceinline__ float lo32(u64 v) { return __uint_as_float((unsigned)v); }
__device__ __forceinline__ float hi32(u64 v) { return __uint_as_float((unsigned)(v >> 32)); }

// ---------------- tf32 tensor-core GEMM ----------------
// C(M,N) = A(M,K) @ B(K,N) + bias0 + bias1.  BM=128 BN=64 BK=32, 256 threads.
__global__ void gemm_tf32(const float* __restrict__ A, const float* __restrict__ B,
                          float* __restrict__ C,
                          const float* __restrict__ bias0, const float* __restrict__ bias1,
                          int M, int N, int K) {
    __shared__ unsigned As[128][36];
    __shared__ unsigned Bs[32][72];

    int tid  = threadIdx.x;
    int lane = tid & 31, wid = tid >> 5;
    int wm = wid & 3, wn = wid >> 2;
    int gid = lane >> 2, tid4 = lane & 3;
    int bm = blockIdx.y, bn = blockIdx.x;

    const float* Ab = A + (size_t)bm * 128 * K;
    const float* Bb = B + (size_t)bn * 64;

    int am[4], akq[4];
#pragma unroll
    for (int it = 0; it < 4; it++) { int f = it * 256 + tid; am[it] = f >> 3; akq[it] = f & 7; }
    int bn4[2], bkk[2];
#pragma unroll
    for (int it = 0; it < 2; it++) { int f = it * 256 + tid; bn4[it] = f & 15; bkk[it] = f >> 4; }

    float acc[2][4][4];
#pragma unroll
    for (int i = 0; i < 2; i++)
#pragma unroll
        for (int j = 0; j < 4; j++)
#pragma unroll
            for (int q = 0; q < 4; q++) acc[i][j][q] = 0.f;

    float4 ar[4], br[2];
#pragma unroll
    for (int it = 0; it < 4; it++)
        ar[it] = *(const float4*)(Ab + (size_t)am[it] * K + akq[it] * 4);
#pragma unroll
    for (int it = 0; it < 2; it++)
        br[it] = *(const float4*)(Bb + (size_t)bkk[it] * N + bn4[it] * 4);

    int nch = K >> 5;
    for (int ch = 0; ch < nch; ch++) {
#pragma unroll
        for (int it = 0; it < 4; it++) {
            unsigned* p = &As[am[it]][akq[it] * 4];
            p[0] = f2tf(ar[it].x); p[1] = f2tf(ar[it].y);
            p[2] = f2tf(ar[it].z); p[3] = f2tf(ar[it].w);
        }
#pragma unroll
        for (int it = 0; it < 2; it++) {
            unsigned* p = &Bs[bkk[it]][bn4[it] * 4];
            p[0] = f2tf(br[it].x); p[1] = f2tf(br[it].y);
            p[2] = f2tf(br[it].z); p[3] = f2tf(br[it].w);
        }
        __syncthreads();
        if (ch + 1 < nch) {
            int k0 = (ch + 1) << 5;
#pragma unroll
            for (int it = 0; it < 4; it++)
                ar[it] = *(const float4*)(Ab + (size_t)am[it] * K + k0 + akq[it] * 4);
#pragma unroll
            for (int it = 0; it < 2; it++)
                br[it] = *(const float4*)(Bb + (size_t)(k0 + bkk[it]) * N + bn4[it] * 4);
        }
#pragma unroll
        for (int kc = 0; kc < 32; kc += 8) {
            unsigned af[2][4], bf[4][2];
#pragma unroll
            for (int s = 0; s < 2; s++) {
                int rm = wm * 32 + s * 16 + gid;
                af[s][0] = As[rm][kc + tid4];
                af[s][1] = As[rm + 8][kc + tid4];
                af[s][2] = As[rm][kc + tid4 + 4];
                af[s][3] = As[rm + 8][kc + tid4 + 4];
            }
#pragma unroll
            for (int s = 0; s < 4; s++) {
                int cb = wn * 32 + s * 8 + gid;
                bf[s][0] = Bs[kc + tid4][cb];
                bf[s][1] = Bs[kc + tid4 + 4][cb];
            }
#pragma unroll
            for (int i = 0; i < 2; i++)
#pragma unroll
                for (int j = 0; j < 4; j++)
                    asm volatile(
                        "mma.sync.aligned.m16n8k8.row.col.f32.tf32.tf32.f32 "
                        "{%0,%1,%2,%3}, {%4,%5,%6,%7}, {%8,%9}, {%0,%1,%2,%3};"
                        : "+f"(acc[i][j][0]), "+f"(acc[i][j][1]),
                          "+f"(acc[i][j][2]), "+f"(acc[i][j][3])
                        : "r"(af[i][0]), "r"(af[i][1]), "r"(af[i][2]), "r"(af[i][3]),
                          "r"(bf[j][0]), "r"(bf[j][1]));
        }
        __syncthreads();
    }

#pragma unroll
    for (int i = 0; i < 2; i++) {
        int r0 = bm * 128 + wm * 32 + i * 16 + gid;
#pragma unroll
        for (int j = 0; j < 4; j++) {
            int col = bn * 64 + wn * 32 + j * 8 + tid4 * 2;
            float bb0 = 0.f, bb1 = 0.f;
            if (bias0) { bb0 += bias0[col]; bb1 += bias0[col + 1]; }
            if (bias1) { bb0 += bias1[col]; bb1 += bias1[col + 1]; }
            float2 v0; v0.x = acc[i][j][0] + bb0; v0.y = acc[i][j][1] + bb1;
            float2 v1; v1.x = acc[i][j][2] + bb0; v1.y = acc[i][j][3] + bb1;
            *(float2*)(C + (size_t)r0 * N + col) = v0;
            *(float2*)(C + (size_t)(r0 + 8) * N + col) = v1;
        }
    }
}

// ---------------- weight pre-pack for the LSTM scan ----------------
__global__ void k_pack(const float* __restrict__ Wall, const float* __restrict__ Wd) {
    int idx = blockIdx.x * 256 + threadIdx.x;
    if (idx >= 16 * 5 * 256 * 16) return;
    int jl = idx & 15;
    int rest = idx >> 4;
    int k = rest & 255;
    int rest2 = rest >> 8;
    int g = rest2 % 5;
    int jblk = rest2 / 5;
    int j = jblk * 16 + jl;
    float v = (g < 4) ? Wall[(size_t)k * G4 + g * DIM + j]
                      : Wd[(size_t)k * DIM + j];
    g_wpack[(size_t)jblk * (5 * 16 * WSTR) + (g * 16 + jl) * WSTR + k] = v;
}

// ---------------- small elementwise kernels ----------------
__global__ void k_tfeat(const float* __restrict__ seq_time, const float* __restrict__ sel_w,
                        const float* __restrict__ sel_b) {
    int idx = blockIdx.x * blockDim.x + threadIdx.x;
    if (idx >= NROWS * 64) return;
    int r = idx >> 6, n = idx & 63;
    float t = seq_time[r] * (1.0f / 180.0f);
    float q = t * sel_w[n] + sel_b[n];
    g_tfeat[idx] = 1.0f - tanhf(q * q);
}

__global__ void k_ek() {
    int idx = blockIdx.x * blockDim.x + threadIdx.x;
    if (idx >= BATCH * DIM) return;
    int b = idx >> 8, j = idx & 255;
    g_ek[idx] = g_x[(size_t)b * SEQL * DIM + j];
}

__global__ void k_init() {
    int idx = blockIdx.x * blockDim.x + threadIdx.x;
    if (idx >= BATCH * DIM) return;
    g_hbuf[0][idx] = 0.f; g_hbuf[1][idx] = 0.f;
    g_cbuf[0][idx] = 0.f; g_cbuf[1][idx] = 0.f;
}

__global__ void k_ekw1(const float* __restrict__ w1_w) {
    int b = blockIdx.x;
    int n = threadIdx.x;  // 64
    float s = 0.f;
    const float* e = g_ek + b * DIM;
#pragma unroll 8
    for (int k = 0; k < DIM; k++) s += e[k] * w1_w[k * 64 + n];
    g_ekw1[b * 64 + n] = s;
}

__global__ void k_attn(const float* __restrict__ w2_w, const float* __restrict__ w2_b) {
    int idx = blockIdx.x * blockDim.x + threadIdx.x;
    if (idx >= BATCH * 199) return;
    int b = idx / 199, s = idx % 199;
    int row = b * SEQL + s;
    const float* a1 = g_att1 + (size_t)row * 64;
    const float* ew = g_ekw1 + b * 64;
    float l0 = w2_b[0], l1 = w2_b[1];
#pragma unroll 8
    for (int n = 0; n < 64; n++) {
        float v = tanhf(a1[n] + ew[n]);
        l0 += v * w2_w[n * 2];
        l1 += v * w2_w[n * 2 + 1];
    }
    float m = fmaxf(l0, l1);
    float e0 = expf(l0 - m), e1 = expf(l1 - m);
    float inv = 1.0f / (e0 + e1);
    g_attn[row * 2]     = e0 * inv;
    g_attn[row * 2 + 1] = e1 * inv;
}

__global__ void k_genx(const float* __restrict__ nn, const float* __restrict__ pn) {
    int idx = blockIdx.x * blockDim.x + threadIdx.x;
    if (idx >= NROWS * DIM) return;
    int j = idx & 255;
    int rs = idx >> 8;
    int b = rs / SEQL, s = rs % SEQL;
    float v;
    if (s == 0) {
        v = g_ek[b * DIM + j];
    } else {
        int row = b * SEQL + (s - 1);
        v = g_ek[b * DIM + j] * g_attn[row * 2] + g_whk[(size_t)row * DIM + j] * g_attn[row * 2 + 1];
    }
    g_genx[idx] = v + nn[idx] - pn[idx];
}

__global__ void k_out(const float* __restrict__ out_w, const float* __restrict__ out_b,
                      float* __restrict__ dst) {
    int b = blockIdx.x;
    int j = threadIdx.x;  // 256
    float h = g_hmax[b * DIM + j];
    __shared__ float s0[256], s1[256];
    s0[j] = h * out_w[j * 2];
    s1[j] = h * out_w[j * 2 + 1];
    __syncthreads();
    for (int off = 128; off > 0; off >>= 1) {
        if (j < off) { s0[j] += s0[j + off]; s1[j] += s1[j + off]; }
        __syncthreads();
    }
    if (j == 0) {
        dst[b * 2]     = s0[0] + out_b[0];
        dst[b * 2 + 1] = s1[0] + out_b[1];
    }
}

// ---------------- persistent LSTM scan ----------------
// 128 blocks (8 batch-tiles x 16 j-tiles), 256 threads, 1 block/SM (co-resident).
// Weights staged to smem ONCE; 200 steps with global H/C ping-pong + grid barrier.
template <bool STORE>
__global__ void __launch_bounds__(256, 1)
lstm_scan(const float* __restrict__ Wd_b) {
    extern __shared__ float sm[];
    float* Hs = sm;                     // [MB][DIM]
    float* Cs = Hs + MB * DIM;          // [MB][DIM]
    float* Ws = Cs + MB * DIM;          // [5][UJ][WSTR]

    int tid = threadIdx.x;
    int bx = blockIdx.x;
    int btile = bx & 7;
    int jblk = bx >> 3;
    int b0 = btile * MB;
    int j0 = jblk * UJ;

    // stage weights once
    const float4* wsrc = (const float4*)(g_wpack + (size_t)jblk * (5 * 16 * WSTR));
    for (int i = tid; i < 5 * 16 * WSTR / 4; i += 256)
        ((float4*)Ws)[i] = wsrc[i];

    int jl = tid & 15;
    int ml = (tid >> 4) * 2;
    int j = j0 + jl;
    float wdb = Wd_b[j];
    float hmax[2] = {-FLT_MAX, -FLT_MAX};

    const ulonglong2* wq0 = (const ulonglong2*)(Ws + (0 * 16 + jl) * WSTR);
    const ulonglong2* wq1 = (const ulonglong2*)(Ws + (1 * 16 + jl) * WSTR);
    const ulonglong2* wq2 = (const ulonglong2*)(Ws + (2 * 16 + jl) * WSTR);
    const ulonglong2* wq3 = (const ulonglong2*)(Ws + (3 * 16 + jl) * WSTR);
    const ulonglong2* wq4 = (const ulonglong2*)(Ws + (4 * 16 + jl) * WSTR);
    const ulonglong2* h0q = (const ulonglong2*)(Hs + ml * DIM);
    const ulonglong2* h1q = (const ulonglong2*)(Hs + (ml + 1) * DIM);
    const ulonglong2* c0q = (const ulonglong2*)(Cs + ml * DIM);
    const ulonglong2* c1q = (const ulonglong2*)(Cs + (ml + 1) * DIM);

    unsigned target = gridDim.x;

    for (int s = 0; s < SEQL; s++) {
        int p = s & 1;
        // stage H,C from global (L2, bypass L1 — cross-SM producers)
        const float4* hin4 = (const float4*)(g_hbuf[p] + b0 * DIM);
        const float4* cin4 = (const float4*)(g_cbuf[p] + b0 * DIM);
        for (int i = tid; i < MB * DIM / 4; i += 256) {
            ((float4*)Hs)[i] = __ldcg(hin4 + i);
            ((float4*)Cs)[i] = __ldcg(cin4 + i);
        }
        __syncthreads();

        u64 ax[5][2], ay[5][2];
#pragma unroll
        for (int g = 0; g < 5; g++) { ax[g][0] = 0; ax[g][1] = 0; ay[g][0] = 0; ay[g][1] = 0; }

#pragma unroll 4
        for (int k4 = 0; k4 < DIM / 4; k4++) {
            ulonglong2 w0 = wq0[k4], w1 = wq1[k4], w2 = wq2[k4], w3 = wq3[k4], w4 = wq4[k4];
            ulonglong2 hv0 = h0q[k4], hv1 = h1q[k4];
            ulonglong2 cv0 = c0q[k4], cv1 = c1q[k4];
            fma2(ax[0][0], hv0.x, w0.x); fma2(ay[0][0], hv0.y, w0.y);
            fma2(ax[0][1], hv1.x, w0.x); fma2(ay[0][1], hv1.y, w0.y);
            fma2(ax[1][0], hv0.x, w1.x); fma2(ay[1][0], hv0.y, w1.y);
            fma2(ax[1][1], hv1.x, w1.x); fma2(ay[1][1], hv1.y, w1.y);
            fma2(ax[2][0], hv0.x, w2.x); fma2(ay[2][0], hv0.y, w2.y);
            fma2(ax[2][1], hv1.x, w2.x); fma2(ay[2][1], hv1.y, w2.y);
            fma2(ax[3][0], hv0.x, w3.x); fma2(ay[3][0], hv0.y, w3.y);
            fma2(ax[3][1], hv1.x, w3.x); fma2(ay[3][1], hv1.y, w3.y);
            fma2(ax[4][0], cv0.x, w4.x); fma2(ay[4][0], cv0.y, w4.y);
            fma2(ax[4][1], cv1.x, w4.x); fma2(ay[4][1], cv1.y, w4.y);
        }

        float av[5][2];
#pragma unroll
        for (int g = 0; g < 5; g++)
#pragma unroll
            for (int r = 0; r < 2; r++)
                av[g][r] = (lo32(ax[g][r]) + hi32(ax[g][r])) + (lo32(ay[g][r]) + hi32(ay[g][r]));

        float* Hdst = g_hbuf[1 - p];
        float* Cdst = g_cbuf[1 - p];
#pragma unroll
        for (int r = 0; r < 2; r++) {
            int b = b0 + ml + r;
            size_t rowi = (size_t)b * SEQL + s;
            const float* xrow = g_xu + rowi * G4;
            float gf = 1.f / (1.f + expf(-(av[0][r] + xrow[j])));
            float gi = 1.f / (1.f + expf(-(av[1][r] + xrow[DIM + j])));
            float go = 1.f / (1.f + expf(-(av[2][r] + xrow[2 * DIM + j])));
            float gc = 1.f / (1.f + expf(-(av[3][r] + xrow[3 * DIM + j])));
            float cs1 = tanhf(av[4][r] + wdb);
            float cold = Cs[(ml + r) * DIM + j];
            float ts = g_tf[rowi * DIM + j];
            float cadj = cold - cs1 + cs1 * ts;
            float cnew = gf * cadj + gi * gc;
            float hnew = go * tanhf(cnew);
            int oi = b * DIM + j;
            Hdst[oi] = hnew;
            Cdst[oi] = cnew;
            if (STORE) g_outh[rowi * DIM + j] = hnew;
            hmax[r] = fmaxf(hmax[r], hnew);
        }

        // grid barrier (release stores, arrive, spin, acquire)
        __threadfence();
        __syncthreads();
        if (tid == 0) {
            atomicAdd(&g_bar, 1u);
            volatile unsigned* bp = &g_bar;
            while (*bp < target) { __nanosleep(64); }
        }
        __syncthreads();
        __threadfence();
        target += gridDim.x;
    }

    int oi0 = (b0 + ml) * DIM + j;
    g_hmax[oi0] = hmax[0];
    g_hmax[oi0 + DIM] = hmax[1];
}

// ---------------- host launcher ----------------
extern "C" void kernel_launch(void* const* d_in, const int* in_sizes, int n_in,
                              void* d_out, int out_size) {
    (void)in_sizes; (void)n_in; (void)out_size;
    const float* input_seqs = (const float*)d_in[0];
    const float* seq_time   = (const float*)d_in[3];
    const float* nn         = (const float*)d_in[6];
    const float* pn         = (const float*)d_in[7];
    const float* emb2_w = (const float*)d_in[9];
    const float* emb2_b = (const float*)d_in[10];
    const float* Wall_w = (const float*)d_in[11];
    const float* Wall_b = (const float*)d_in[12];
    const float* Uall_w = (const float*)d_in[13];
    const float* Uall_b = (const float*)d_in[14];
    const float* Wd_w   = (const float*)d_in[15];
    const float* Wd_b   = (const float*)d_in[16];
    const float* time_w = (const float*)d_in[17];
    const float* time_b = (const float*)d_in[18];
    const float* sel_w  = (const float*)d_in[19];
    const float* sel_b  = (const float*)d_in[20];
    const float* whk_w  = (const float*)d_in[21];
    const float* whk_b  = (const float*)d_in[22];
    const float* w1_w   = (const float*)d_in[23];
    const float* w1_b   = (const float*)d_in[24];
    const float* w2_w   = (const float*)d_in[25];
    const float* w2_b   = (const float*)d_in[26];
    const float* out_w  = (const float*)d_in[27];
    const float* out_b  = (const float*)d_in[28];
    float* out = (float*)d_out;

    float *px, *ptfeat, *ptf, *pxu, *pouth, *pwhk, *patt1, *pgenx;
    unsigned* pbar;
    cudaGetSymbolAddress((void**)&px, g_x);
    cudaGetSymbolAddress((void**)&ptfeat, g_tfeat);
    cudaGetSymbolAddress((void**)&ptf, g_tf);
    cudaGetSymbolAddress((void**)&pxu, g_xu);
    cudaGetSymbolAddress((void**)&pouth, g_outh);
    cudaGetSymbolAddress((void**)&pwhk, g_whk);
    cudaGetSymbolAddress((void**)&patt1, g_att1);
    cudaGetSymbolAddress((void**)&pgenx, g_genx);
    cudaGetSymbolAddress((void**)&pbar, g_bar);

    const int SMEM_SCAN = (2 * MB * DIM + 5 * UJ * WSTR) * 4;  // 148736 B
    cudaFuncSetAttribute((const void*)lstm_scan<true>,
                         cudaFuncAttributeMaxDynamicSharedMemorySize, SMEM_SCAN);
    cudaFuncSetAttribute((const void*)lstm_scan<false>,
                         cudaFuncAttributeMaxDynamicSharedMemorySize, SMEM_SCAN);

    dim3 t256(256);

    // pack recurrence weights (cheap, replayed)
    k_pack<<<(16 * 5 * 256 * 16) / 256, t256>>>(Wall_w, Wd_w);

    // time feature
    k_tfeat<<<(NROWS * 64 + 255) / 256, t256>>>(seq_time, sel_w, sel_b);
    gemm_tf32<<<dim3(DIM / 64, NROWS / 128), t256>>>(ptfeat, time_w, ptf, time_b, nullptr,
                                                     NROWS, DIM, 64);
    // x = input @ emb2 + b
    gemm_tf32<<<dim3(DIM / 64, NROWS / 128), t256>>>(input_seqs, emb2_w, px, emb2_b, nullptr,
                                                     NROWS, DIM, DIM);
    k_ek<<<(BATCH * DIM + 255) / 256, t256>>>();
    // xu1 = x @ Uall + (Uall_b + Wall_b)
    gemm_tf32<<<dim3(G4 / 64, NROWS / 128), t256>>>(px, Uall_w, pxu, Uall_b, Wall_b,
                                                    NROWS, G4, DIM);
    // LSTM scan 1 (persistent)
    k_init<<<(BATCH * DIM + 255) / 256, t256>>>();
    cudaMemsetAsync(pbar, 0, sizeof(unsigned));
    lstm_scan<true><<<NBLK, t256, SMEM_SCAN>>>(Wd_b);
    k_out<<<BATCH, t256>>>(out_w, out_b, out);  // out -> [0, 512)

    // whk, attention, gen_x
    gemm_tf32<<<dim3(DIM / 64, NROWS / 128), t256>>>(pouth, whk_w, pwhk, whk_b, nullptr,
                                                     NROWS, DIM, DIM);
    k_ekw1<<<BATCH, 64>>>(w1_w);
    gemm_tf32<<<dim3(1, NROWS / 128), t256>>>(pwhk, w1_w + 256 * 64, patt1, w1_b, nullptr,
                                              NROWS, 64, DIM);
    k_attn<<<(BATCH * 199 + 255) / 256, t256>>>(w2_w, w2_b);
    k_genx<<<(NROWS * DIM + 255) / 256, t256>>>(nn, pn);

    // xu2 = gen_x @ Uall + (Uall_b + Wall_b)
    gemm_tf32<<<dim3(G4 / 64, NROWS / 128), t256>>>(pgenx, Uall_w, pxu, Uall_b, Wall_b,
                                                    NROWS, G4, DIM);
    // LSTM scan 2 (persistent, no per-step h store)
    k_init<<<(BATCH * DIM + 255) / 256, t256>>>();
    cudaMemsetAsync(pbar, 0, sizeof(unsigned));
    lstm_scan<false><<<NBLK, t256, SMEM_SCAN>>>(Wd_b);
    k_out<<<BATCH, t256>>>(out_w, out_b, out + 512);  // gen_out -> [512, 1024)

    // pass-throughs: predicted_noise then normal_noise
    cudaMemcpyAsync(out + 1024, pn, (size_t)NROWS * DIM * sizeof(float),
                    cudaMemcpyDeviceToDevice);
    cudaMemcpyAsync(out + 1024 + (size_t)NROWS * DIM, nn, (size_t)NROWS * DIM * sizeof(float),
                    cudaMemcpyDeviceToDevice);
}

// round 4
// speedup vs baseline: 2.4681x; 1.3950x over previous
#include <cuda_runtime.h>
#include <math.h>
#include <float.h>

#define BATCH 256
#define SEQL  200
#define DIM   256
#define G4    1024
#define NROWS (BATCH*SEQL)   // 51200
#define WSTR  260            // padded k-stride for packed weights
#define MB 32
#define UJ 16
#define NBLK 128             // 8 batch-tiles x 16 j-tiles

typedef unsigned long long u64;

// ---------------- device scratch (no allocations allowed) ----------------
__device__ float g_x[NROWS*DIM];
__device__ float g_tfeat[NROWS*64];
__device__ float g_tf[NROWS*DIM];
__device__ float g_xu[NROWS*G4];
__device__ float g_outh[NROWS*DIM];
__device__ float g_whk[NROWS*DIM];
__device__ float g_att1[NROWS*64];
__device__ float g_attn[NROWS*2];
__device__ float g_genx[NROWS*DIM];
__device__ float g_ek[BATCH*DIM];
__device__ float g_ekw1[BATCH*64];
__device__ float g_hbuf[2][BATCH*DIM];
__device__ float g_cbuf[2][BATCH*DIM];
__device__ float g_hmax[BATCH*DIM];
__device__ float g_wpack[16*5*16*WSTR];   // [jblk][g][jl][k(+pad)]
__device__ unsigned g_bar;                // grid barrier counter (reset by k_pack)

// ---------------- tf32 helpers ----------------
__device__ __forceinline__ unsigned f2tf(float f) {
    unsigned u; asm("cvt.rna.tf32.f32 %0, %1;" : "=r"(u) : "f"(f)); return u;
}
__device__ __forceinline__ void fma2(u64 &d, u64 a, u64 b) {
    asm("fma.rn.f32x2 %0, %1, %2, %3;" : "=l"(d) : "l"(a), "l"(b), "l"(d));
}
__device__ __forceinline__ float lo32(u64 v) { return __uint_as_float((unsigned)v); }
__device__ __forceinline__ float hi32(u64 v) { return __uint_as_float((unsigned)(v >> 32)); }

// ---------------- tf32 tensor-core GEMM ----------------
__global__ void gemm_tf32(const float* __restrict__ A, const float* __restrict__ B,
                          float* __restrict__ C,
                          const float* __restrict__ bias0, const float* __restrict__ bias1,
                          int M, int N, int K) {
    __shared__ unsigned As[128][36];
    __shared__ unsigned Bs[32][72];

    int tid  = threadIdx.x;
    int lane = tid & 31, wid = tid >> 5;
    int wm = wid & 3, wn = wid >> 2;
    int gid = lane >> 2, tid4 = lane & 3;
    int bm = blockIdx.y, bn = blockIdx.x;

    const float* Ab = A + (size_t)bm * 128 * K;
    const float* Bb = B + (size_t)bn * 64;

    int am[4], akq[4];
#pragma unroll
    for (int it = 0; it < 4; it++) { int f = it * 256 + tid; am[it] = f >> 3; akq[it] = f & 7; }
    int bn4[2], bkk[2];
#pragma unroll
    for (int it = 0; it < 2; it++) { int f = it * 256 + tid; bn4[it] = f & 15; bkk[it] = f >> 4; }

    float acc[2][4][4];
#pragma unroll
    for (int i = 0; i < 2; i++)
#pragma unroll
        for (int j = 0; j < 4; j++)
#pragma unroll
            for (int q = 0; q < 4; q++) acc[i][j][q] = 0.f;

    float4 ar[4], br[2];
#pragma unroll
    for (int it = 0; it < 4; it++)
        ar[it] = *(const float4*)(Ab + (size_t)am[it] * K + akq[it] * 4);
#pragma unroll
    for (int it = 0; it < 2; it++)
        br[it] = *(const float4*)(Bb + (size_t)bkk[it] * N + bn4[it] * 4);

    int nch = K >> 5;
    for (int ch = 0; ch < nch; ch++) {
#pragma unroll
        for (int it = 0; it < 4; it++) {
            unsigned* p = &As[am[it]][akq[it] * 4];
            p[0] = f2tf(ar[it].x); p[1] = f2tf(ar[it].y);
            p[2] = f2tf(ar[it].z); p[3] = f2tf(ar[it].w);
        }
#pragma unroll
        for (int it = 0; it < 2; it++) {
            unsigned* p = &Bs[bkk[it]][bn4[it] * 4];
            p[0] = f2tf(br[it].x); p[1] = f2tf(br[it].y);
            p[2] = f2tf(br[it].z); p[3] = f2tf(br[it].w);
        }
        __syncthreads();
        if (ch + 1 < nch) {
            int k0 = (ch + 1) << 5;
#pragma unroll
            for (int it = 0; it < 4; it++)
                ar[it] = *(const float4*)(Ab + (size_t)am[it] * K + k0 + akq[it] * 4);
#pragma unroll
            for (int it = 0; it < 2; it++)
                br[it] = *(const float4*)(Bb + (size_t)(k0 + bkk[it]) * N + bn4[it] * 4);
        }
#pragma unroll
        for (int kc = 0; kc < 32; kc += 8) {
            unsigned af[2][4], bf[4][2];
#pragma unroll
            for (int s = 0; s < 2; s++) {
                int rm = wm * 32 + s * 16 + gid;
                af[s][0] = As[rm][kc + tid4];
                af[s][1] = As[rm + 8][kc + tid4];
                af[s][2] = As[rm][kc + tid4 + 4];
                af[s][3] = As[rm + 8][kc + tid4 + 4];
            }
#pragma unroll
            for (int s = 0; s < 4; s++) {
                int cb = wn * 32 + s * 8 + gid;
                bf[s][0] = Bs[kc + tid4][cb];
                bf[s][1] = Bs[kc + tid4 + 4][cb];
            }
#pragma unroll
            for (int i = 0; i < 2; i++)
#pragma unroll
                for (int j = 0; j < 4; j++)
                    asm volatile(
                        "mma.sync.aligned.m16n8k8.row.col.f32.tf32.tf32.f32 "
                        "{%0,%1,%2,%3}, {%4,%5,%6,%7}, {%8,%9}, {%0,%1,%2,%3};"
                        : "+f"(acc[i][j][0]), "+f"(acc[i][j][1]),
                          "+f"(acc[i][j][2]), "+f"(acc[i][j][3])
                        : "r"(af[i][0]), "r"(af[i][1]), "r"(af[i][2]), "r"(af[i][3]),
                          "r"(bf[j][0]), "r"(bf[j][1]));
        }
        __syncthreads();
    }

#pragma unroll
    for (int i = 0; i < 2; i++) {
        int r0 = bm * 128 + wm * 32 + i * 16 + gid;
#pragma unroll
        for (int j = 0; j < 4; j++) {
            int col = bn * 64 + wn * 32 + j * 8 + tid4 * 2;
            float bb0 = 0.f, bb1 = 0.f;
            if (bias0) { bb0 += bias0[col]; bb1 += bias0[col + 1]; }
            if (bias1) { bb0 += bias1[col]; bb1 += bias1[col + 1]; }
            float2 v0; v0.x = acc[i][j][0] + bb0; v0.y = acc[i][j][1] + bb1;
            float2 v1; v1.x = acc[i][j][2] + bb0; v1.y = acc[i][j][3] + bb1;
            *(float2*)(C + (size_t)r0 * N + col) = v0;
            *(float2*)(C + (size_t)(r0 + 8) * N + col) = v1;
        }
    }
}

// ---------------- weight pre-pack for the LSTM scan (also resets barrier) ----
__global__ void k_pack(const float* __restrict__ Wall, const float* __restrict__ Wd) {
    if (blockIdx.x == 0 && threadIdx.x == 0) g_bar = 0;
    int idx = blockIdx.x * 256 + threadIdx.x;
    if (idx >= 16 * 5 * 256 * 16) return;
    int jl = idx & 15;
    int rest = idx >> 4;
    int k = rest & 255;
    int rest2 = rest >> 8;
    int g = rest2 % 5;
    int jblk = rest2 / 5;
    int j = jblk * 16 + jl;
    float v = (g < 4) ? Wall[(size_t)k * G4 + g * DIM + j]
                      : Wd[(size_t)k * DIM + j];
    g_wpack[(size_t)jblk * (5 * 16 * WSTR) + (g * 16 + jl) * WSTR + k] = v;
}

// ---------------- small elementwise kernels ----------------
__global__ void k_tfeat(const float* __restrict__ seq_time, const float* __restrict__ sel_w,
                        const float* __restrict__ sel_b) {
    int idx = blockIdx.x * blockDim.x + threadIdx.x;
    if (idx >= NROWS * 64) return;
    int r = idx >> 6, n = idx & 63;
    float t = seq_time[r] * (1.0f / 180.0f);
    float q = t * sel_w[n] + sel_b[n];
    g_tfeat[idx] = 1.0f - tanhf(q * q);
}

__global__ void k_ek() {
    int idx = blockIdx.x * blockDim.x + threadIdx.x;
    if (idx >= BATCH * DIM) return;
    int b = idx >> 8, j = idx & 255;
    g_ek[idx] = g_x[(size_t)b * SEQL * DIM + j];
}

__global__ void k_ekw1(const float* __restrict__ w1_w) {
    int b = blockIdx.x;
    int n = threadIdx.x;  // 64
    float s = 0.f;
    const float* e = g_ek + b * DIM;
#pragma unroll 8
    for (int k = 0; k < DIM; k++) s += e[k] * w1_w[k * 64 + n];
    g_ekw1[b * 64 + n] = s;
}

__global__ void k_attn(const float* __restrict__ w2_w, const float* __restrict__ w2_b) {
    int idx = blockIdx.x * blockDim.x + threadIdx.x;
    if (idx >= BATCH * 199) return;
    int b = idx / 199, s = idx % 199;
    int row = b * SEQL + s;
    const float* a1 = g_att1 + (size_t)row * 64;
    const float* ew = g_ekw1 + b * 64;
    float l0 = w2_b[0], l1 = w2_b[1];
#pragma unroll 8
    for (int n = 0; n < 64; n++) {
        float v = tanhf(a1[n] + ew[n]);
        l0 += v * w2_w[n * 2];
        l1 += v * w2_w[n * 2 + 1];
    }
    float m = fmaxf(l0, l1);
    float e0 = expf(l0 - m), e1 = expf(l1 - m);
    float inv = 1.0f / (e0 + e1);
    g_attn[row * 2]     = e0 * inv;
    g_attn[row * 2 + 1] = e1 * inv;
}

__global__ void k_genx(const float* __restrict__ nn, const float* __restrict__ pn) {
    int idx = blockIdx.x * blockDim.x + threadIdx.x;
    if (idx >= NROWS * DIM) return;
    int j = idx & 255;
    int rs = idx >> 8;
    int b = rs / SEQL, s = rs % SEQL;
    float v;
    if (s == 0) {
        v = g_ek[b * DIM + j];
    } else {
        int row = b * SEQL + (s - 1);
        v = g_ek[b * DIM + j] * g_attn[row * 2] + g_whk[(size_t)row * DIM + j] * g_attn[row * 2 + 1];
    }
    g_genx[idx] = v + nn[idx] - pn[idx];
}

__global__ void k_out(const float* __restrict__ out_w, const float* __restrict__ out_b,
                      float* __restrict__ dst) {
    int b = blockIdx.x;
    int j = threadIdx.x;  // 256
    float h = g_hmax[b * DIM + j];
    __shared__ float s0[256], s1[256];
    s0[j] = h * out_w[j * 2];
    s1[j] = h * out_w[j * 2 + 1];
    __syncthreads();
    for (int off = 128; off > 0; off >>= 1) {
        if (j < off) { s0[j] += s0[j + off]; s1[j] += s1[j + off]; }
        __syncthreads();
    }
    if (j == 0) {
        dst[b * 2]     = s0[0] + out_b[0];
        dst[b * 2 + 1] = s1[0] + out_b[1];
    }
}

// ---------------- persistent LSTM scan (software-pipelined) ----------------
// 128 blocks (8 batch-tiles x 16 j-tiles), 256 threads, 1 block/SM.
#define LD_SET(W, H, C, i) \
    W[0] = wq0[i]; W[1] = wq1[i]; W[2] = wq2[i]; W[3] = wq3[i]; W[4] = wq4[i]; \
    H[0] = h0q[i]; H[1] = h1q[i]; C[0] = c0q[i]; C[1] = c1q[i];

#define FMA_SET(W, H, C) \
    fma2(ax[0][0], H[0].x, W[0].x); fma2(ay[0][0], H[0].y, W[0].y); \
    fma2(ax[0][1], H[1].x, W[0].x); fma2(ay[0][1], H[1].y, W[0].y); \
    fma2(ax[1][0], H[0].x, W[1].x); fma2(ay[1][0], H[0].y, W[1].y); \
    fma2(ax[1][1], H[1].x, W[1].x); fma2(ay[1][1], H[1].y, W[1].y); \
    fma2(ax[2][0], H[0].x, W[2].x); fma2(ay[2][0], H[0].y, W[2].y); \
    fma2(ax[2][1], H[1].x, W[2].x); fma2(ay[2][1], H[1].y, W[2].y); \
    fma2(ax[3][0], H[0].x, W[3].x); fma2(ay[3][0], H[0].y, W[3].y); \
    fma2(ax[3][1], H[1].x, W[3].x); fma2(ay[3][1], H[1].y, W[3].y); \
    fma2(ax[4][0], C[0].x, W[4].x); fma2(ay[4][0], C[0].y, W[4].y); \
    fma2(ax[4][1], C[1].x, W[4].x); fma2(ay[4][1], C[1].y, W[4].y);

template <bool STORE>
__global__ void __launch_bounds__(256, 1)
lstm_scan(const float* __restrict__ Wd_b, unsigned barBase) {
    extern __shared__ float sm[];
    float* Hs = sm;                     // [MB][DIM]
    float* Cs = Hs + MB * DIM;          // [MB][DIM]
    float* Ws = Cs + MB * DIM;          // [5][UJ][WSTR]

    int tid = threadIdx.x;
    int bx = blockIdx.x;
    int btile = bx & 7;
    int jblk = bx >> 3;
    int b0 = btile * MB;
    int j0 = jblk * UJ;

    // stage weights once
    const float4* wsrc = (const float4*)(g_wpack + (size_t)jblk * (5 * 16 * WSTR));
    for (int i = tid; i < 5 * 16 * WSTR / 4; i += 256)
        ((float4*)Ws)[i] = wsrc[i];

    int jl = tid & 15;
    int ml = (tid >> 4) * 2;
    int j = j0 + jl;
    float wdb = Wd_b[j];
    float hmax0 = -FLT_MAX, hmax1 = -FLT_MAX;

    const ulonglong2* wq0 = (const ulonglong2*)(Ws + (0 * 16 + jl) * WSTR);
    const ulonglong2* wq1 = (const ulonglong2*)(Ws + (1 * 16 + jl) * WSTR);
    const ulonglong2* wq2 = (const ulonglong2*)(Ws + (2 * 16 + jl) * WSTR);
    const ulonglong2* wq3 = (const ulonglong2*)(Ws + (3 * 16 + jl) * WSTR);
    const ulonglong2* wq4 = (const ulonglong2*)(Ws + (4 * 16 + jl) * WSTR);
    const ulonglong2* h0q = (const ulonglong2*)(Hs + ml * DIM);
    const ulonglong2* h1q = (const ulonglong2*)(Hs + (ml + 1) * DIM);
    const ulonglong2* c0q = (const ulonglong2*)(Cs + ml * DIM);
    const ulonglong2* c1q = (const ulonglong2*)(Cs + (ml + 1) * DIM);

    unsigned target = barBase + NBLK;
    size_t row0base = (size_t)(b0 + ml) * SEQL;

    for (int s = 0; s < SEQL; s++) {
        int p = s & 1;

        // ---- prefetch this step's globals (independent of gate loop) ----
        size_t row0 = row0base + s;
        size_t row1 = row0 + SEQL;
        const float* x0 = g_xu + row0 * G4 + j;
        const float* x1 = g_xu + row1 * G4 + j;
        float xf0 = __ldg(x0);           float xf1 = __ldg(x1);
        float xi0 = __ldg(x0 + DIM);     float xi1 = __ldg(x1 + DIM);
        float xo0 = __ldg(x0 + 2*DIM);   float xo1 = __ldg(x1 + 2*DIM);
        float xc0 = __ldg(x0 + 3*DIM);   float xc1 = __ldg(x1 + 3*DIM);
        float ts0 = __ldg(g_tf + row0 * DIM + j);
        float ts1 = __ldg(g_tf + row1 * DIM + j);

        u64 ax[5][2], ay[5][2];
#pragma unroll
        for (int g = 0; g < 5; g++) { ax[g][0] = 0; ax[g][1] = 0; ay[g][0] = 0; ay[g][1] = 0; }

        if (s > 0) {
            // stage H,C from global (L2, cross-SM producers)
            const float4* hin4 = (const float4*)(g_hbuf[p] + b0 * DIM);
            const float4* cin4 = (const float4*)(g_cbuf[p] + b0 * DIM);
            for (int i = tid; i < MB * DIM / 4; i += 256) {
                ((float4*)Hs)[i] = __ldcg(hin4 + i);
                ((float4*)Cs)[i] = __ldcg(cin4 + i);
            }
            __syncthreads();

            // software-pipelined gate GEMM
            ulonglong2 wA[5], hA[2], cA[2], wB[5], hB[2], cB[2];
            LD_SET(wA, hA, cA, 0);
            for (int k4 = 0; k4 < DIM / 4; k4 += 2) {
                LD_SET(wB, hB, cB, k4 + 1);
                FMA_SET(wA, hA, cA);
                if (k4 + 2 < DIM / 4) { LD_SET(wA, hA, cA, k4 + 2); }
                FMA_SET(wB, hB, cB);
            }
        }

        float av[5][2];
#pragma unroll
        for (int g = 0; g < 5; g++) {
            av[g][0] = (lo32(ax[g][0]) + hi32(ax[g][0])) + (lo32(ay[g][0]) + hi32(ay[g][0]));
            av[g][1] = (lo32(ax[g][1]) + hi32(ax[g][1])) + (lo32(ay[g][1]) + hi32(ay[g][1]));
        }

        float* Hdst = g_hbuf[1 - p];
        float* Cdst = g_cbuf[1 - p];

        float cold0 = (s > 0) ? Cs[ml * DIM + j]       : 0.f;
        float cold1 = (s > 0) ? Cs[(ml + 1) * DIM + j] : 0.f;

        {
            float gf = 1.f / (1.f + expf(-(av[0][0] + xf0)));
            float gi = 1.f / (1.f + expf(-(av[1][0] + xi0)));
            float go = 1.f / (1.f + expf(-(av[2][0] + xo0)));
            float gc = 1.f / (1.f + expf(-(av[3][0] + xc0)));
            float cs1 = tanhf(av[4][0] + wdb);
            float cadj = cold0 - cs1 + cs1 * ts0;
            float cnew = gf * cadj + gi * gc;
            float hnew = go * tanhf(cnew);
            int oi = (b0 + ml) * DIM + j;
            Hdst[oi] = hnew; Cdst[oi] = cnew;
            if (STORE) g_outh[row0 * DIM + j] = hnew;
            hmax0 = fmaxf(hmax0, hnew);
        }
        {
            float gf = 1.f / (1.f + expf(-(av[0][1] + xf1)));
            float gi = 1.f / (1.f + expf(-(av[1][1] + xi1)));
            float go = 1.f / (1.f + expf(-(av[2][1] + xo1)));
            float gc = 1.f / (1.f + expf(-(av[3][1] + xc1)));
            float cs1 = tanhf(av[4][1] + wdb);
            float cadj = cold1 - cs1 + cs1 * ts1;
            float cnew = gf * cadj + gi * gc;
            float hnew = go * tanhf(cnew);
            int oi = (b0 + ml + 1) * DIM + j;
            Hdst[oi] = hnew; Cdst[oi] = cnew;
            if (STORE) g_outh[row1 * DIM + j] = hnew;
            hmax1 = fmaxf(hmax1, hnew);
        }

        // grid barrier (skip after the final step)
        if (s < SEQL - 1) {
            __threadfence();
            __syncthreads();
            if (tid == 0) {
                atomicAdd(&g_bar, 1u);
                volatile unsigned* bp = &g_bar;
                while (*bp < target) { __nanosleep(64); }
            }
            __syncthreads();
            __threadfence();
            target += NBLK;
        }
    }

    int oi0 = (b0 + ml) * DIM + j;
    g_hmax[oi0] = hmax0;
    g_hmax[oi0 + DIM] = hmax1;
}

// ---------------- host launcher ----------------
extern "C" void kernel_launch(void* const* d_in, const int* in_sizes, int n_in,
                              void* d_out, int out_size) {
    (void)in_sizes; (void)n_in; (void)out_size;
    const float* input_seqs = (const float*)d_in[0];
    const float* seq_time   = (const float*)d_in[3];
    const float* nn         = (const float*)d_in[6];
    const float* pn         = (const float*)d_in[7];
    const float* emb2_w = (const float*)d_in[9];
    const float* emb2_b = (const float*)d_in[10];
    const float* Wall_w = (const float*)d_in[11];
    const float* Wall_b = (const float*)d_in[12];
    const float* Uall_w = (const float*)d_in[13];
    const float* Uall_b = (const float*)d_in[14];
    const float* Wd_w   = (const float*)d_in[15];
    const float* Wd_b   = (const float*)d_in[16];
    const float* time_w = (const float*)d_in[17];
    const float* time_b = (const float*)d_in[18];
    const float* sel_w  = (const float*)d_in[19];
    const float* sel_b  = (const float*)d_in[20];
    const float* whk_w  = (const float*)d_in[21];
    const float* whk_b  = (const float*)d_in[22];
    const float* w1_w   = (const float*)d_in[23];
    const float* w1_b   = (const float*)d_in[24];
    const float* w2_w   = (const float*)d_in[25];
    const float* w2_b   = (const float*)d_in[26];
    const float* out_w  = (const float*)d_in[27];
    const float* out_b  = (const float*)d_in[28];
    float* out = (float*)d_out;

    float *px, *ptfeat, *ptf, *pxu, *pouth, *pwhk, *patt1, *pgenx;
    cudaGetSymbolAddress((void**)&px, g_x);
    cudaGetSymbolAddress((void**)&ptfeat, g_tfeat);
    cudaGetSymbolAddress((void**)&ptf, g_tf);
    cudaGetSymbolAddress((void**)&pxu, g_xu);
    cudaGetSymbolAddress((void**)&pouth, g_outh);
    cudaGetSymbolAddress((void**)&pwhk, g_whk);
    cudaGetSymbolAddress((void**)&patt1, g_att1);
    cudaGetSymbolAddress((void**)&pgenx, g_genx);

    const int SMEM_SCAN = (2 * MB * DIM + 5 * UJ * WSTR) * 4;  // 148736 B
    cudaFuncSetAttribute((const void*)lstm_scan<true>,
                         cudaFuncAttributeMaxDynamicSharedMemorySize, SMEM_SCAN);
    cudaFuncSetAttribute((const void*)lstm_scan<false>,
                         cudaFuncAttributeMaxDynamicSharedMemorySize, SMEM_SCAN);

    dim3 t256(256);

    // launch order matters for ncu (-s 5 -c 1 profiles launch #5 = lstm_scan<true>)
    // 0: pack weights + reset barrier
    k_pack<<<(16 * 5 * 256 * 16) / 256, t256>>>(Wall_w, Wd_w);
    // 1: time feature elementwise
    k_tfeat<<<(NROWS * 64 + 255) / 256, t256>>>(seq_time, sel_w, sel_b);
    // 2: tf = tfeat @ time_w + time_b
    gemm_tf32<<<dim3(DIM / 64, NROWS / 128), t256>>>(ptfeat, time_w, ptf, time_b, nullptr,
                                                     NROWS, DIM, 64);
    // 3: x = input @ emb2 + b
    gemm_tf32<<<dim3(DIM / 64, NROWS / 128), t256>>>(input_seqs, emb2_w, px, emb2_b, nullptr,
                                                     NROWS, DIM, DIM);
    // 4: xu1 = x @ Uall + (Uall_b + Wall_b)
    gemm_tf32<<<dim3(G4 / 64, NROWS / 128), t256>>>(px, Uall_w, pxu, Uall_b, Wall_b,
                                                    NROWS, G4, DIM);
    // 5: LSTM scan 1 (persistent; s==0 handled internally, no init needed)
    lstm_scan<true><<<NBLK, t256, SMEM_SCAN>>>(Wd_b, 0u);
    // 6: e_k extraction
    k_ek<<<(BATCH * DIM + 255) / 256, t256>>>();
    // 7: out head
    k_out<<<BATCH, t256>>>(out_w, out_b, out);  // out -> [0, 512)

    // whk, attention, gen_x
    gemm_tf32<<<dim3(DIM / 64, NROWS / 128), t256>>>(pouth, whk_w, pwhk, whk_b, nullptr,
                                                     NROWS, DIM, DIM);
    k_ekw1<<<BATCH, 64>>>(w1_w);
    gemm_tf32<<<dim3(1, NROWS / 128), t256>>>(pwhk, w1_w + 256 * 64, patt1, w1_b, nullptr,
                                              NROWS, 64, DIM);
    k_attn<<<(BATCH * 199 + 255) / 256, t256>>>(w2_w, w2_b);
    k_genx<<<(NROWS * DIM + 255) / 256, t256>>>(nn, pn);

    // xu2 = gen_x @ Uall + (Uall_b + Wall_b)
    gemm_tf32<<<dim3(G4 / 64, NROWS / 128), t256>>>(pgenx, Uall_w, pxu, Uall_b, Wall_b,
                                                    NROWS, G4, DIM);
    // LSTM scan 2 (scan1 consumed 199 barriers of NBLK each)
    lstm_scan<false><<<NBLK, t256, SMEM_SCAN>>>(Wd_b, 199u * NBLK);
    k_out<<<BATCH, t256>>>(out_w, out_b, out + 512);  // gen_out -> [512, 1024)

    // pass-throughs: predicted_noise then normal_noise
    cudaMemcpyAsync(out + 1024, pn, (size_t)NROWS * DIM * sizeof(float),
                    cudaMemcpyDeviceToDevice);
    cudaMemcpyAsync(out + 1024 + (size_t)NROWS * DIM, nn, (size_t)NROWS * DIM * sizeof(float),
                    cudaMemcpyDeviceToDevice);
}

// round 5
// speedup vs baseline: 3.8638x; 1.5655x over previous
#include <cuda_runtime.h>
#include <math.h>
#include <float.h>

#define BATCH 256
#define SEQL  200
#define DIM   256
#define G4    1024
#define NROWS (BATCH*SEQL)   // 51200
#define MB 32
#define NBLK 128             // 8 batch-tiles x 16 j-tiles

// scan smem geometry
#define HSTR 260             // [32][260] tf32 H/C (260%32=4 -> conflict-free A frags)
#define WN   88              // [256][88] tf32 weights (88%32=24 -> conflict-free B frags)

typedef unsigned long long u64;

// ---------------- device scratch (no allocations allowed) ----------------
__device__ float g_x[NROWS*DIM];
__device__ float g_tfeat[NROWS*64];
__device__ float g_tf[NROWS*DIM];
__device__ float g_xu[NROWS*G4];
__device__ float g_outh[NROWS*DIM];
__device__ float g_whk[NROWS*DIM];
__device__ float g_att1[NROWS*64];
__device__ float g_attn[NROWS*2];
__device__ float g_genx[NROWS*DIM];
__device__ float g_ek[BATCH*DIM];
__device__ float g_ekw1[BATCH*64];
__device__ float g_hbuf[2][BATCH*DIM];
__device__ float g_cbuf[2][BATCH*DIM];
__device__ float g_hmax[BATCH*DIM];
__device__ float g_wpack[16*256*WN];      // [jblk][k][n] tf32 bits
__device__ unsigned g_bar;                // grid barrier counter (reset by k_prep)

// ---------------- tf32 helpers ----------------
__device__ __forceinline__ unsigned f2tf(float f) {
    unsigned u; asm("cvt.rna.tf32.f32 %0, %1;" : "=r"(u) : "f"(f)); return u;
}

#define MMA8(acc, a0, a1, a2, a3, b0, b1) \
    asm volatile("mma.sync.aligned.m16n8k8.row.col.f32.tf32.tf32.f32 " \
                 "{%0,%1,%2,%3}, {%4,%5,%6,%7}, {%8,%9}, {%0,%1,%2,%3};" \
                 : "+f"(acc[0]), "+f"(acc[1]), "+f"(acc[2]), "+f"(acc[3]) \
                 : "r"(a0), "r"(a1), "r"(a2), "r"(a3), "r"(b0), "r"(b1))

// ---------------- tf32 tensor-core GEMM (parallel projections) ----------------
__global__ void gemm_tf32(const float* __restrict__ A, const float* __restrict__ B,
                          float* __restrict__ C,
                          const float* __restrict__ bias0, const float* __restrict__ bias1,
                          int M, int N, int K) {
    __shared__ unsigned As[128][36];
    __shared__ unsigned Bs[32][72];

    int tid  = threadIdx.x;
    int lane = tid & 31, wid = tid >> 5;
    int wm = wid & 3, wn = wid >> 2;
    int gid = lane >> 2, tid4 = lane & 3;
    int bm = blockIdx.y, bn = blockIdx.x;

    const float* Ab = A + (size_t)bm * 128 * K;
    const float* Bb = B + (size_t)bn * 64;

    int am[4], akq[4];
#pragma unroll
    for (int it = 0; it < 4; it++) { int f = it * 256 + tid; am[it] = f >> 3; akq[it] = f & 7; }
    int bn4[2], bkk[2];
#pragma unroll
    for (int it = 0; it < 2; it++) { int f = it * 256 + tid; bn4[it] = f & 15; bkk[it] = f >> 4; }

    float acc[2][4][4];
#pragma unroll
    for (int i = 0; i < 2; i++)
#pragma unroll
        for (int j = 0; j < 4; j++)
#pragma unroll
            for (int q = 0; q < 4; q++) acc[i][j][q] = 0.f;

    float4 ar[4], br[2];
#pragma unroll
    for (int it = 0; it < 4; it++)
        ar[it] = *(const float4*)(Ab + (size_t)am[it] * K + akq[it] * 4);
#pragma unroll
    for (int it = 0; it < 2; it++)
        br[it] = *(const float4*)(Bb + (size_t)bkk[it] * N + bn4[it] * 4);

    int nch = K >> 5;
    for (int ch = 0; ch < nch; ch++) {
#pragma unroll
        for (int it = 0; it < 4; it++) {
            unsigned* p = &As[am[it]][akq[it] * 4];
            p[0] = f2tf(ar[it].x); p[1] = f2tf(ar[it].y);
            p[2] = f2tf(ar[it].z); p[3] = f2tf(ar[it].w);
        }
#pragma unroll
        for (int it = 0; it < 2; it++) {
            unsigned* p = &Bs[bkk[it]][bn4[it] * 4];
            p[0] = f2tf(br[it].x); p[1] = f2tf(br[it].y);
            p[2] = f2tf(br[it].z); p[3] = f2tf(br[it].w);
        }
        __syncthreads();
        if (ch + 1 < nch) {
            int k0 = (ch + 1) << 5;
#pragma unroll
            for (int it = 0; it < 4; it++)
                ar[it] = *(const float4*)(Ab + (size_t)am[it] * K + k0 + akq[it] * 4);
#pragma unroll
            for (int it = 0; it < 2; it++)
                br[it] = *(const float4*)(Bb + (size_t)(k0 + bkk[it]) * N + bn4[it] * 4);
        }
#pragma unroll
        for (int kc = 0; kc < 32; kc += 8) {
            unsigned af[2][4], bf[4][2];
#pragma unroll
            for (int s = 0; s < 2; s++) {
                int rm = wm * 32 + s * 16 + gid;
                af[s][0] = As[rm][kc + tid4];
                af[s][1] = As[rm + 8][kc + tid4];
                af[s][2] = As[rm][kc + tid4 + 4];
                af[s][3] = As[rm + 8][kc + tid4 + 4];
            }
#pragma unroll
            for (int s = 0; s < 4; s++) {
                int cb = wn * 32 + s * 8 + gid;
                bf[s][0] = Bs[kc + tid4][cb];
                bf[s][1] = Bs[kc + tid4 + 4][cb];
            }
#pragma unroll
            for (int i = 0; i < 2; i++)
#pragma unroll
                for (int j = 0; j < 4; j++)
                    MMA8(acc[i][j], af[i][0], af[i][1], af[i][2], af[i][3],
                         bf[j][0], bf[j][1]);
        }
        __syncthreads();
    }

#pragma unroll
    for (int i = 0; i < 2; i++) {
        int r0 = bm * 128 + wm * 32 + i * 16 + gid;
#pragma unroll
        for (int j = 0; j < 4; j++) {
            int col = bn * 64 + wn * 32 + j * 8 + tid4 * 2;
            float bb0 = 0.f, bb1 = 0.f;
            if (bias0) { bb0 += bias0[col]; bb1 += bias0[col + 1]; }
            if (bias1) { bb0 += bias1[col]; bb1 += bias1[col + 1]; }
            float2 v0; v0.x = acc[i][j][0] + bb0; v0.y = acc[i][j][1] + bb1;
            float2 v1; v1.x = acc[i][j][2] + bb0; v1.y = acc[i][j][3] + bb1;
            *(float2*)(C + (size_t)r0 * N + col) = v0;
            *(float2*)(C + (size_t)(r0 + 8) * N + col) = v1;
        }
    }
}

// ---------------- fused prep: barrier reset + tfeat + weight pack ----------------
// grid = 12800 (tfeat) + 1408 (pack) = 14208 blocks of 256.
__global__ void k_prep(const float* __restrict__ seq_time, const float* __restrict__ sel_w,
                       const float* __restrict__ sel_b,
                       const float* __restrict__ Wall, const float* __restrict__ Wd) {
    int bid = blockIdx.x;
    if (bid == 0 && threadIdx.x == 0) g_bar = 0;
    if (bid < 12800) {
        int idx = bid * 256 + threadIdx.x;
        int r = idx >> 6, n = idx & 63;
        float t = seq_time[r] * (1.0f / 180.0f);
        float q = t * sel_w[n] + sel_b[n];
        g_tfeat[idx] = 1.0f - tanhf(q * q);
    } else {
        int idx = (bid - 12800) * 256 + threadIdx.x;
        if (idx < 16 * 256 * WN) {
            int n = idx % WN;
            int rest = idx / WN;
            int k = rest & 255;
            int jblk = rest >> 8;
            float v = 0.f;
            if (n < 64)      v = Wall[(size_t)k * G4 + (n >> 4) * DIM + jblk * 16 + (n & 15)];
            else if (n < 80) v = Wd[(size_t)k * DIM + jblk * 16 + (n - 64)];
            g_wpack[idx] = __uint_as_float(f2tf(v));
        }
    }
}

// ---------------- small elementwise kernels ----------------
__global__ void k_ek() {
    int idx = blockIdx.x * blockDim.x + threadIdx.x;
    if (idx >= BATCH * DIM) return;
    int b = idx >> 8, j = idx & 255;
    g_ek[idx] = g_x[(size_t)b * SEQL * DIM + j];
}

__global__ void k_ekw1(const float* __restrict__ w1_w) {
    int b = blockIdx.x;
    int n = threadIdx.x;  // 64
    float s = 0.f;
    const float* e = g_ek + b * DIM;
#pragma unroll 8
    for (int k = 0; k < DIM; k++) s += e[k] * w1_w[k * 64 + n];
    g_ekw1[b * 64 + n] = s;
}

__global__ void k_attn(const float* __restrict__ w2_w, const float* __restrict__ w2_b) {
    int idx = blockIdx.x * blockDim.x + threadIdx.x;
    if (idx >= BATCH * 199) return;
    int b = idx / 199, s = idx % 199;
    int row = b * SEQL + s;
    const float* a1 = g_att1 + (size_t)row * 64;
    const float* ew = g_ekw1 + b * 64;
    float l0 = w2_b[0], l1 = w2_b[1];
#pragma unroll 8
    for (int n = 0; n < 64; n++) {
        float v = tanhf(a1[n] + ew[n]);
        l0 += v * w2_w[n * 2];
        l1 += v * w2_w[n * 2 + 1];
    }
    float m = fmaxf(l0, l1);
    float e0 = expf(l0 - m), e1 = expf(l1 - m);
    float inv = 1.0f / (e0 + e1);
    g_attn[row * 2]     = e0 * inv;
    g_attn[row * 2 + 1] = e1 * inv;
}

__global__ void k_genx(const float* __restrict__ nn, const float* __restrict__ pn) {
    int idx = blockIdx.x * blockDim.x + threadIdx.x;
    if (idx >= NROWS * DIM) return;
    int j = idx & 255;
    int rs = idx >> 8;
    int b = rs / SEQL, s = rs % SEQL;
    float v;
    if (s == 0) {
        v = g_ek[b * DIM + j];
    } else {
        int row = b * SEQL + (s - 1);
        v = g_ek[b * DIM + j] * g_attn[row * 2] + g_whk[(size_t)row * DIM + j] * g_attn[row * 2 + 1];
    }
    g_genx[idx] = v + nn[idx] - pn[idx];
}

__global__ void k_out(const float* __restrict__ out_w, const float* __restrict__ out_b,
                      float* __restrict__ dst) {
    int b = blockIdx.x;
    int j = threadIdx.x;  // 256
    float h = g_hmax[b * DIM + j];
    __shared__ float s0[256], s1[256];
    s0[j] = h * out_w[j * 2];
    s1[j] = h * out_w[j * 2 + 1];
    __syncthreads();
    for (int off = 128; off > 0; off >>= 1) {
        if (j < off) { s0[j] += s0[j + off]; s1[j] += s1[j + off]; }
        __syncthreads();
    }
    if (j == 0) {
        dst[b * 2]     = s0[0] + out_b[0];
        dst[b * 2 + 1] = s1[0] + out_b[1];
    }
}

// ---------------- persistent LSTM scan with tensor-core gate GEMM ----------------
// 128 blocks (8 batch-tiles x 16 j-tiles), 256 threads, 1 block/SM.
// Per block per step: gates[32 batch][80] = [H|C](32x256 tf32) @ W(256x80 tf32).
template <bool STORE>
__global__ void __launch_bounds__(256, 1)
lstm_scan(const float* __restrict__ Wd_b, unsigned barBase) {
    extern __shared__ float sm[];
    float* Hs  = sm;                   // [32][HSTR] tf32 bits
    float* Cts = Hs + 32 * HSTR;       // [32][HSTR] tf32 bits
    float* Wsm = Cts + 32 * HSTR;      // [256][WN] tf32 bits
    float* Gs  = Wsm + 256 * WN;       // [32][WN] f32 gate preacts

    int tid = threadIdx.x;
    int bx = blockIdx.x;
    int btile = bx & 7, jblk = bx >> 3;
    int b0 = btile * MB, j0 = jblk * 16;

    // stage weights once (already tf32 bits)
    {
        const float4* src = (const float4*)(g_wpack + (size_t)jblk * 256 * WN);
        float4* dst = (float4*)Wsm;
        for (int i = tid; i < 256 * WN / 4; i += 256) dst[i] = src[i];
    }

    int lane = tid & 31, wid = tid >> 5;
    int fr = lane >> 2, fc = lane & 3;       // fragment row/col
    int mt = wid & 1, q = wid >> 1;          // m-tile, n-quarter
    int m16 = mt * 16;
    bool has3 = (q < 2);
    int n0 = q * 8 + fr, n1 = (q + 4) * 8 + fr, n2 = (8 + q) * 8 + fr;

    int jl = tid & 15, ml = (tid >> 4) * 2;
    int j = j0 + jl;
    float wdb = Wd_b[j];
    float hmax0 = -FLT_MAX, hmax1 = -FLT_MAX;

    unsigned target = barBase + NBLK;
    size_t row0base = (size_t)(b0 + ml) * SEQL;

    for (int s = 0; s < SEQL; s++) {
        int p = s & 1;
        size_t row0 = row0base + s, row1 = row0 + SEQL;
        const float* x0 = g_xu + row0 * G4 + j;
        const float* x1 = g_xu + row1 * G4 + j;
        float xf0 = __ldg(x0);          float xf1 = __ldg(x1);
        float xi0 = __ldg(x0 + DIM);    float xi1 = __ldg(x1 + DIM);
        float xo0 = __ldg(x0 + 2*DIM);  float xo1 = __ldg(x1 + 2*DIM);
        float xc0 = __ldg(x0 + 3*DIM);  float xc1 = __ldg(x1 + 3*DIM);
        float ts0 = __ldg(g_tf + row0 * DIM + j);
        float ts1 = __ldg(g_tf + row1 * DIM + j);
        float cold0 = 0.f, cold1 = 0.f;

        float av[5][2];
#pragma unroll
        for (int g = 0; g < 5; g++) { av[g][0] = 0.f; av[g][1] = 0.f; }

        if (s > 0) {
            cold0 = __ldcg(g_cbuf[p] + (b0 + ml) * DIM + j);
            cold1 = __ldcg(g_cbuf[p] + (b0 + ml + 1) * DIM + j);

            // stage H, C as tf32 into smem
            const float4* hin4 = (const float4*)(g_hbuf[p] + b0 * DIM);
            const float4* cin4 = (const float4*)(g_cbuf[p] + b0 * DIM);
            for (int i = tid; i < MB * DIM / 4; i += 256) {
                float4 h = __ldcg(hin4 + i);
                float4 c = __ldcg(cin4 + i);
                int bb = i >> 6;
                int c4 = (i & 63) * 4;
                float* hd = Hs + bb * HSTR + c4;
                float* cd = Cts + bb * HSTR + c4;
                hd[0] = __uint_as_float(f2tf(h.x)); hd[1] = __uint_as_float(f2tf(h.y));
                hd[2] = __uint_as_float(f2tf(h.z)); hd[3] = __uint_as_float(f2tf(h.w));
                cd[0] = __uint_as_float(f2tf(c.x)); cd[1] = __uint_as_float(f2tf(c.y));
                cd[2] = __uint_as_float(f2tf(c.z)); cd[3] = __uint_as_float(f2tf(c.w));
            }
            __syncthreads();

            // tensor-core gate GEMM
            float acc0[4] = {0,0,0,0}, acc1[4] = {0,0,0,0}, acc2[4] = {0,0,0,0};
            const float* Ar0 = Hs + (m16 + fr) * HSTR;
            const float* Ar1 = Hs + (m16 + fr + 8) * HSTR;
            const float* Cr0 = Cts + (m16 + fr) * HSTR;
            const float* Cr1 = Cts + (m16 + fr + 8) * HSTR;
#pragma unroll 4
            for (int k0 = 0; k0 < 256; k0 += 8) {
                unsigned a0 = __float_as_uint(Ar0[k0 + fc]);
                unsigned a1 = __float_as_uint(Ar1[k0 + fc]);
                unsigned a2 = __float_as_uint(Ar0[k0 + fc + 4]);
                unsigned a3 = __float_as_uint(Ar1[k0 + fc + 4]);
                unsigned b00 = __float_as_uint(Wsm[(k0 + fc) * WN + n0]);
                unsigned b01 = __float_as_uint(Wsm[(k0 + fc + 4) * WN + n0]);
                unsigned b10 = __float_as_uint(Wsm[(k0 + fc) * WN + n1]);
                unsigned b11 = __float_as_uint(Wsm[(k0 + fc + 4) * WN + n1]);
                MMA8(acc0, a0, a1, a2, a3, b00, b01);
                MMA8(acc1, a0, a1, a2, a3, b10, b11);
                if (has3) {
                    unsigned ca0 = __float_as_uint(Cr0[k0 + fc]);
                    unsigned ca1 = __float_as_uint(Cr1[k0 + fc]);
                    unsigned ca2 = __float_as_uint(Cr0[k0 + fc + 4]);
                    unsigned ca3 = __float_as_uint(Cr1[k0 + fc + 4]);
                    unsigned b20 = __float_as_uint(Wsm[(k0 + fc) * WN + n2]);
                    unsigned b21 = __float_as_uint(Wsm[(k0 + fc + 4) * WN + n2]);
                    MMA8(acc2, ca0, ca1, ca2, ca3, b20, b21);
                }
            }

            // store gate preacts to smem scratch
            {
                int nc0 = q * 8 + 2 * fc;
                *(float2*)(Gs + (m16 + fr) * WN + nc0)     = make_float2(acc0[0], acc0[1]);
                *(float2*)(Gs + (m16 + fr + 8) * WN + nc0) = make_float2(acc0[2], acc0[3]);
                int nc1 = (q + 4) * 8 + 2 * fc;
                *(float2*)(Gs + (m16 + fr) * WN + nc1)     = make_float2(acc1[0], acc1[1]);
                *(float2*)(Gs + (m16 + fr + 8) * WN + nc1) = make_float2(acc1[2], acc1[3]);
                if (has3) {
                    int nc2 = (8 + q) * 8 + 2 * fc;
                    *(float2*)(Gs + (m16 + fr) * WN + nc2)     = make_float2(acc2[0], acc2[1]);
                    *(float2*)(Gs + (m16 + fr + 8) * WN + nc2) = make_float2(acc2[2], acc2[3]);
                }
            }
            __syncthreads();

#pragma unroll
            for (int g = 0; g < 5; g++) {
                int n = (g < 4) ? g * 16 + jl : 64 + jl;
                av[g][0] = Gs[ml * WN + n];
                av[g][1] = Gs[(ml + 1) * WN + n];
            }
        }

        float* Hdst = g_hbuf[1 - p];
        float* Cdst = g_cbuf[1 - p];
        {
            float gf = 1.f / (1.f + expf(-(av[0][0] + xf0)));
            float gi = 1.f / (1.f + expf(-(av[1][0] + xi0)));
            float go = 1.f / (1.f + expf(-(av[2][0] + xo0)));
            float gc = 1.f / (1.f + expf(-(av[3][0] + xc0)));
            float cs1 = tanhf(av[4][0] + wdb);
            float cadj = cold0 - cs1 + cs1 * ts0;
            float cnew = gf * cadj + gi * gc;
            float hnew = go * tanhf(cnew);
            int oi = (b0 + ml) * DIM + j;
            Hdst[oi] = hnew; Cdst[oi] = cnew;
            if (STORE) g_outh[row0 * DIM + j] = hnew;
            hmax0 = fmaxf(hmax0, hnew);
        }
        {
            float gf = 1.f / (1.f + expf(-(av[0][1] + xf1)));
            float gi = 1.f / (1.f + expf(-(av[1][1] + xi1)));
            float go = 1.f / (1.f + expf(-(av[2][1] + xo1)));
            float gc = 1.f / (1.f + expf(-(av[3][1] + xc1)));
            float cs1 = tanhf(av[4][1] + wdb);
            float cadj = cold1 - cs1 + cs1 * ts1;
            float cnew = gf * cadj + gi * gc;
            float hnew = go * tanhf(cnew);
            int oi = (b0 + ml + 1) * DIM + j;
            Hdst[oi] = hnew; Cdst[oi] = cnew;
            if (STORE) g_outh[row1 * DIM + j] = hnew;
            hmax1 = fmaxf(hmax1, hnew);
        }

        if (s < SEQL - 1) {
            __threadfence();
            __syncthreads();
            if (tid == 0) {
                atomicAdd(&g_bar, 1u);
                volatile unsigned* bp = &g_bar;
                while (*bp < target) { __nanosleep(32); }
            }
            __syncthreads();
            __threadfence();
            target += NBLK;
        }
    }

    int oi0 = (b0 + ml) * DIM + j;
    g_hmax[oi0] = hmax0;
    g_hmax[oi0 + DIM] = hmax1;
}

// ---------------- host launcher ----------------
extern "C" void kernel_launch(void* const* d_in, const int* in_sizes, int n_in,
                              void* d_out, int out_size) {
    (void)in_sizes; (void)n_in; (void)out_size;
    const float* input_seqs = (const float*)d_in[0];
    const float* seq_time   = (const float*)d_in[3];
    const float* nn         = (const float*)d_in[6];
    const float* pn         = (const float*)d_in[7];
    const float* emb2_w = (const float*)d_in[9];
    const float* emb2_b = (const float*)d_in[10];
    const float* Wall_w = (const float*)d_in[11];
    const float* Wall_b = (const float*)d_in[12];
    const float* Uall_w = (const float*)d_in[13];
    const float* Uall_b = (const float*)d_in[14];
    const float* Wd_w   = (const float*)d_in[15];
    const float* Wd_b   = (const float*)d_in[16];
    const float* time_w = (const float*)d_in[17];
    const float* time_b = (const float*)d_in[18];
    const float* sel_w  = (const float*)d_in[19];
    const float* sel_b  = (const float*)d_in[20];
    const float* whk_w  = (const float*)d_in[21];
    const float* whk_b  = (const float*)d_in[22];
    const float* w1_w   = (const float*)d_in[23];
    const float* w1_b   = (const float*)d_in[24];
    const float* w2_w   = (const float*)d_in[25];
    const float* w2_b   = (const float*)d_in[26];
    const float* out_w  = (const float*)d_in[27];
    const float* out_b  = (const float*)d_in[28];
    float* out = (float*)d_out;

    float *px, *ptfeat, *ptf, *pxu, *pouth, *pwhk, *patt1, *pgenx;
    cudaGetSymbolAddress((void**)&px, g_x);
    cudaGetSymbolAddress((void**)&ptfeat, g_tfeat);
    cudaGetSymbolAddress((void**)&ptf, g_tf);
    cudaGetSymbolAddress((void**)&pxu, g_xu);
    cudaGetSymbolAddress((void**)&pouth, g_outh);
    cudaGetSymbolAddress((void**)&pwhk, g_whk);
    cudaGetSymbolAddress((void**)&patt1, g_att1);
    cudaGetSymbolAddress((void**)&pgenx, g_genx);

    const int SMEM_SCAN = (2 * 32 * HSTR + 256 * WN + 32 * WN) * 4;  // ~168 KB
    cudaFuncSetAttribute((const void*)lstm_scan<true>,
                         cudaFuncAttributeMaxDynamicSharedMemorySize, SMEM_SCAN);
    cudaFuncSetAttribute((const void*)lstm_scan<false>,
                         cudaFuncAttributeMaxDynamicSharedMemorySize, SMEM_SCAN);

    dim3 t256(256);

    // 1: prep (barrier reset + tfeat + tf32 weight pack)
    k_prep<<<12800 + 1408, t256>>>(seq_time, sel_w, sel_b, Wall_w, Wd_w);
    // 2: tf = tfeat @ time_w + time_b
    gemm_tf32<<<dim3(DIM / 64, NROWS / 128), t256>>>(ptfeat, time_w, ptf, time_b, nullptr,
                                                     NROWS, DIM, 64);
    // 3: x = input @ emb2 + b
    gemm_tf32<<<dim3(DIM / 64, NROWS / 128), t256>>>(input_seqs, emb2_w, px, emb2_b, nullptr,
                                                     NROWS, DIM, DIM);
    // 4: xu1 = x @ Uall + (Uall_b + Wall_b)
    gemm_tf32<<<dim3(G4 / 64, NROWS / 128), t256>>>(px, Uall_w, pxu, Uall_b, Wall_b,
                                                    NROWS, G4, DIM);
    // 5: LSTM scan 1  (ncu -s 5 profiles this launch)
    lstm_scan<true><<<NBLK, t256, SMEM_SCAN>>>(Wd_b, 0u);
    // e_k + out head
    k_ek<<<(BATCH * DIM + 255) / 256, t256>>>();
    k_out<<<BATCH, t256>>>(out_w, out_b, out);  // out -> [0, 512)

    // whk, attention, gen_x
    gemm_tf32<<<dim3(DIM / 64, NROWS / 128), t256>>>(pouth, whk_w, pwhk, whk_b, nullptr,
                                                     NROWS, DIM, DIM);
    k_ekw1<<<BATCH, 64>>>(w1_w);
    gemm_tf32<<<dim3(1, NROWS / 128), t256>>>(pwhk, w1_w + 256 * 64, patt1, w1_b, nullptr,
                                              NROWS, 64, DIM);
    k_attn<<<(BATCH * 199 + 255) / 256, t256>>>(w2_w, w2_b);
    k_genx<<<(NROWS * DIM + 255) / 256, t256>>>(nn, pn);

    // xu2 = gen_x @ Uall + (Uall_b + Wall_b)
    gemm_tf32<<<dim3(G4 / 64, NROWS / 128), t256>>>(pgenx, Uall_w, pxu, Uall_b, Wall_b,
                                                    NROWS, G4, DIM);
    // LSTM scan 2 (scan1 consumed 199*NBLK barrier arrivals)
    lstm_scan<false><<<NBLK, t256, SMEM_SCAN>>>(Wd_b, 199u * NBLK);
    k_out<<<BATCH, t256>>>(out_w, out_b, out + 512);  // gen_out -> [512, 1024)

    // pass-throughs: predicted_noise then normal_noise
    cudaMemcpyAsync(out + 1024, pn, (size_t)NROWS * DIM * sizeof(float),
                    cudaMemcpyDeviceToDevice);
    cudaMemcpyAsync(out + 1024 + (size_t)NROWS * DIM, nn, (size_t)NROWS * DIM * sizeof(float),
                    cudaMemcpyDeviceToDevice);
}